// round 12
// baseline (speedup 1.0000x reference)
#include <cuda_runtime.h>
#include <cuda_fp16.h>
#include <math.h>
#include <stdint.h>

#define NN 100000
#define NROWS 100096   // 782 * 128
#define EE 1600000
#define BB 4096
#define ML 50
#define NPAD 100352    // 98 * 1024

#define MIN_NORM 1e-15f
#define EPSC 1e-7f
#define MAX_NORMC 1000000.0f

// ---------------- persistent scratch ----------------
__device__ float d_K, d_sqrtK;
__device__ float d_ub1[128], d_ubg1[128], d_ubg2[128];
__device__ float d_la  [(size_t)NROWS * 128];
__device__ float d_la1 [(size_t)NN * 128];
__device__ float d_la2 [(size_t)NN * 128];
__device__ __half2 d_gh [(size_t)NN * 64];   // fp16 pre-aggregation tangents
__device__ float d_lx  [(size_t)NROWS * 128];
__device__ float d_Wcat[128 * 256];

// CSR scratch
__device__ int  d_cnt[NPAD];
__device__ int  d_rowptr[NPAD];
__device__ int  d_woff[NN];
__device__ int  d_bsum[98];
__device__ int  d_bscan[98];
__device__ int2 d_epack[EE];

// ---------------- warp helpers ----------------
__device__ __forceinline__ float wsum(float v) {
#pragma unroll
    for (int o = 16; o > 0; o >>= 1) v += __shfl_xor_sync(0xffffffffu, v, o);
    return v;
}

__device__ __forceinline__ float sdot(const float* a, const float* b, int lane) {
    float s = a[1] * b[1] + a[2] * b[2] + a[3] * b[3];
    if (lane != 0) s += a[0] * b[0];
    return wsum(s);
}

__device__ __forceinline__ float hpoint(const float in[4], float out[4], int lane,
                                        float K, float sqrtK) {
    float ss = sdot(in, in, lane);
    float xn = fmaxf(sqrtf(ss), MIN_NORM);
    float th = xn / sqrtK;
    float s  = sqrtK * sinhf(th) / xn;
#pragma unroll
    for (int i = 0; i < 4; i++) out[i] = s * in[i];
    float ss2 = sdot(out, out, lane);
    float p0  = sqrtf(fmaxf(K + ss2, EPSC));
    if (lane == 0) out[0] = p0;
    return p0;
}

__device__ __forceinline__ void logmap0p(const float p[4], float p0, float out[4],
                                         int lane, float sqrtK) {
    float ssp = sdot(p, p, lane);
    float yn  = fmaxf(sqrtf(ssp), MIN_NORM);
    float t   = fmaxf(p0 / sqrtK, 1.0f + EPSC);
    float sc  = sqrtK * acoshf(t) / yn;
#pragma unroll
    for (int i = 0; i < 4; i++) out[i] = sc * p[i];
    if (lane == 0) out[0] = 0.0f;
}

__device__ __forceinline__ float mobius_add_pt(const float p[4], float p0,
                                               const float* __restrict__ u,
                                               float out[4], int lane,
                                               float K, float sqrtK) {
    float uv[4];
#pragma unroll
    for (int i = 0; i < 4; i++) uv[i] = u[lane * 4 + i];
    float ssp   = sdot(p, p, lane);
    float yn    = fmaxf(sqrtf(ssp), MIN_NORM);
    float du    = sdot(p, uv, lane);
    float alpha = du / (yn * sqrtK);
    float beta  = alpha * (sqrtK - p0) / yn;
    float w[4];
#pragma unroll
    for (int i = 0; i < 4; i++) w[i] = uv[i] - beta * p[i];
    float ux = sdot(p, w, lane);
    float w0 = ux / fmaxf(p0, EPSC);
    float wss   = sdot(w, w, lane);
    float md    = wss - w0 * w0;
    float normu = fminf(sqrtf(fmaxf(md, EPSC)), MAX_NORMC);
    float th    = fmaxf(normu / sqrtK, MIN_NORM);
    float ch    = coshf(th);
    float sh    = sinhf(th) / th;
#pragma unroll
    for (int i = 0; i < 4; i++) out[i] = ch * p[i] + sh * w[i];
    float rss = sdot(out, out, lane);
    float q0  = sqrtf(fmaxf(K + rss, EPSC));
    if (lane == 0) out[0] = q0;
    return q0;
}

__device__ __forceinline__ void store_g_h(int row, int lane, const float v[4]) {
    __half2* p = d_gh + (size_t)row * 64 + lane * 2;
    p[0] = __floats2half2_rn(v[0], v[1]);
    p[1] = __floats2half2_rn(v[2], v[3]);
}

// ---------------- K0 ----------------
__device__ void bias_u(const float* b, float* u, float K, float sqrtK) {
    float ss = 0.0f;
    for (int i = 1; i < 128; i++) ss += b[i] * b[i];
    float xn = fmaxf(sqrtf(ss), MIN_NORM);
    float th = xn / sqrtK;
    float s  = sqrtK * sinhf(th) / xn;
    float y[128];
    float ss2 = 0.0f;
    for (int i = 1; i < 128; i++) { y[i] = s * b[i]; ss2 += y[i] * y[i]; }
    float x0 = sqrtf(fmaxf(K + ss2, EPSC));
    float yn = fmaxf(sqrtf(ss2), MIN_NORM);
    float t  = fmaxf(x0 / sqrtK, 1.0f + EPSC);
    float sc = sqrtK * acoshf(t) / yn;
    u[0] = 0.0f;
    for (int i = 1; i < 128; i++) u[i] = sc * y[i];
}

__global__ void k0(const float* __restrict__ rc, const float* __restrict__ b1,
                   const float* __restrict__ bg1, const float* __restrict__ bg2) {
    float c = log1pf(expf(rc[0])) + 1e-5f;
    float K = 1.0f / c, sq = sqrtf(K);
    d_K = K; d_sqrtK = sq;
    bias_u(b1,  d_ub1,  K, sq);
    bias_u(bg1, d_ubg1, K, sq);
    bias_u(bg2, d_ubg2, K, sq);
}

__global__ void prep_wcat(const float* __restrict__ Lin1, const float* __restrict__ g1w) {
    int j = blockIdx.x * 256 + threadIdx.x;
    int k = j >> 8, col = j & 255;
    d_Wcat[j] = (col < 128) ? Lin1[(k + 1) * 128 + col]
                            : g1w[(k + 1) * 128 + (col - 128)];
}

// ---------------- CSR build ----------------
__global__ void zero_cnt() {
    int i = blockIdx.x * 256 + threadIdx.x;
    if (i < NPAD) d_cnt[i] = 0;
}

__global__ void hist(const int* __restrict__ rows) {
    int e = blockIdx.x * 256 + threadIdx.x;
    if (e < EE) atomicAdd(&d_cnt[rows[e]], 1);
}

__global__ void __launch_bounds__(1024) scan1() {
    __shared__ int sh[1024];
    int t = threadIdx.x;
    int i = blockIdx.x * 1024 + t;
    int v = d_cnt[i];
    sh[t] = v;
    __syncthreads();
#pragma unroll
    for (int off = 1; off < 1024; off <<= 1) {
        int x = (t >= off) ? sh[t - off] : 0;
        __syncthreads();
        sh[t] += x;
        __syncthreads();
    }
    d_rowptr[i] = sh[t] - v;
    if (t == 1023) d_bsum[blockIdx.x] = sh[1023];
}

__global__ void __launch_bounds__(128) scan2() {
    __shared__ int sh[128];
    int t = threadIdx.x;
    int v = (t < 98) ? d_bsum[t] : 0;
    sh[t] = v;
    __syncthreads();
#pragma unroll
    for (int off = 1; off < 128; off <<= 1) {
        int x = (t >= off) ? sh[t - off] : 0;
        __syncthreads();
        sh[t] += x;
        __syncthreads();
    }
    if (t < 98) d_bscan[t] = sh[t] - v;
}

__global__ void scan3() {
    int i = blockIdx.x * 256 + threadIdx.x;
    if (i < NPAD) {
        int v = d_rowptr[i] + d_bscan[i >> 10];
        d_rowptr[i] = v;
        if (i < NN) d_woff[i] = v;
    }
}

__global__ void scatter(const int* __restrict__ rows, const int* __restrict__ cols,
                        const float* __restrict__ vals) {
    int e = blockIdx.x * 256 + threadIdx.x;
    if (e < EE) {
        int r = rows[e];
        int pos = atomicAdd(&d_woff[r], 1);
        d_epack[pos] = make_int2(cols[e], __float_as_int(vals[e]));
    }
}

// ---------------- K1 ----------------
__global__ void __launch_bounds__(256) k1(const float* __restrict__ A1) {
    int node = blockIdx.x * 8 + (threadIdx.x >> 5);
    int lane = threadIdx.x & 31;
    float K = d_K, sq = d_sqrtK;
    const float* row = A1 + (size_t)node * 129 + 1;
    float x[4];
#pragma unroll
    for (int i = 0; i < 4; i++) x[i] = row[lane * 4 + i];
    float ss = wsum(x[0]*x[0] + x[1]*x[1] + x[2]*x[2] + x[3]*x[3]);
    float xn = fmaxf(sqrtf(ss), MIN_NORM);
    float th = xn / sq;
    float s  = sq * sinhf(th) / xn;
    float y[4];
#pragma unroll
    for (int i = 0; i < 4; i++) y[i] = s * x[i];
    float ss2 = wsum(y[0]*y[0] + y[1]*y[1] + y[2]*y[2] + y[3]*y[3]);
    float x0 = sqrtf(fmaxf(K + ss2, EPSC));
    float yn = fmaxf(sqrtf(ss2), MIN_NORM);
    float t  = fmaxf(x0 / sq, 1.0f + EPSC);
    float sc = sq * acoshf(t) / yn;
    float* o = d_la + (size_t)node * 128 + lane * 4;
#pragma unroll
    for (int i = 0; i < 4; i++) o[i] = sc * y[i];
}

// ---------------- TF32 MMA GEMM + fused hyperbolic-chain epilogue ----------------
// modes: 0 = t1-chain (ub1 -> la1, la2), 1 = p1-chain (ubg1 -> d_gh),
//        2 = q-chain (ubg2 -> d_gh).  gemm1: mode = blockIdx.y (0,1); gemm2: mode 2.
#define SASTR 36
#define SBSTR 136
#define SA_FL (128 * SASTR)   // 4608 floats per buffer
#define SB_FL (32 * SBSTR)    // 4352 floats per buffer
#define SMEM_BYTES ((2 * (SA_FL + SB_FL)) * 4)   // 71680
#define CSTR 132              // epilogue C-tile stride (128*132*4 = 67584 <= 71680)

__device__ __forceinline__ uint32_t f2tf32(float f) {
    uint32_t r;
    asm("cvt.rna.tf32.f32 %0, %1;" : "=r"(r) : "f"(f));
    return r;
}

__device__ __forceinline__ void mma8(float c[4], uint32_t a0, uint32_t a1,
                                     uint32_t a2, uint32_t a3,
                                     uint32_t b0, uint32_t b1) {
    asm volatile(
        "mma.sync.aligned.m16n8k8.row.col.f32.tf32.tf32.f32 "
        "{%0,%1,%2,%3}, {%4,%5,%6,%7}, {%8,%9}, {%0,%1,%2,%3};"
        : "+f"(c[0]), "+f"(c[1]), "+f"(c[2]), "+f"(c[3])
        : "r"(a0), "r"(a1), "r"(a2), "r"(a3), "r"(b0), "r"(b1));
}

__device__ __forceinline__ void cpasync16(uint32_t saddr, const void* gptr) {
    asm volatile("cp.async.ca.shared.global [%0], [%1], 16;" :: "r"(saddr), "l"(gptr));
}

__global__ void __launch_bounds__(256, 2) mma_gemm(const float* __restrict__ A,
                                                   const float* __restrict__ W,
                                                   const float* __restrict__ nparam,
                                                   int mode_base, int N) {
    extern __shared__ float smem[];
    float* sA[2] = { smem, smem + SA_FL };
    float* sB[2] = { smem + 2 * SA_FL, smem + 2 * SA_FL + SB_FL };

    int tid  = threadIdx.x;
    int lane = tid & 31;
    int w    = tid >> 5;
    int wm0  = (w & 3) * 32;
    int wn0  = (w >> 2) * 64;
    int r0   = blockIdx.x * 128;
    int n0   = blockIdx.y * 128;

    int a_row = tid >> 1, a_half = (tid & 1) * 16;
    int b_k   = tid >> 3, b_seg  = (tid & 7) * 16;

    const float* Agp = A + (size_t)(r0 + a_row) * 128 + a_half;
    const float* Wgp = W + (size_t)b_k * N + n0 + b_seg;

    auto load_tile = [&](int buf, int k0) {
        uint32_t sa = (uint32_t)__cvta_generic_to_shared(sA[buf] + a_row * SASTR + a_half);
        const float* ag = Agp + k0;
#pragma unroll
        for (int i = 0; i < 4; i++) cpasync16(sa + i * 16, ag + i * 4);
        uint32_t sb = (uint32_t)__cvta_generic_to_shared(sB[buf] + b_k * SBSTR + b_seg);
        const float* bg = Wgp + (size_t)k0 * N;
#pragma unroll
        for (int i = 0; i < 4; i++) cpasync16(sb + i * 16, bg + i * 4);
        asm volatile("cp.async.commit_group;");
    };

    float acc[2][8][4];
#pragma unroll
    for (int am = 0; am < 2; am++)
#pragma unroll
        for (int n = 0; n < 8; n++)
#pragma unroll
            for (int i = 0; i < 4; i++) acc[am][n][i] = 0.0f;

    load_tile(0, 0);
    asm volatile("cp.async.wait_group 0;" ::: "memory");
    __syncthreads();

#pragma unroll
    for (int t = 0; t < 4; t++) {
        int cur = t & 1, nxt = cur ^ 1;
        if (t < 3) load_tile(nxt, (t + 1) * 32);

        const float* pA = sA[cur];
        const float* pB = sB[cur];
#pragma unroll
        for (int ks = 0; ks < 4; ks++) {
            int kb = ks * 8;
            uint32_t ah[2][4], al[2][4];
#pragma unroll
            for (int am = 0; am < 2; am++) {
                int m = wm0 + am * 16 + (lane >> 2);
                int c = kb + (lane & 3);
                float f0 = pA[m * SASTR + c];
                float f1 = pA[(m + 8) * SASTR + c];
                float f2 = pA[m * SASTR + c + 4];
                float f3 = pA[(m + 8) * SASTR + c + 4];
                ah[am][0] = f2tf32(f0); al[am][0] = f2tf32(f0 - __uint_as_float(ah[am][0]));
                ah[am][1] = f2tf32(f1); al[am][1] = f2tf32(f1 - __uint_as_float(ah[am][1]));
                ah[am][2] = f2tf32(f2); al[am][2] = f2tf32(f2 - __uint_as_float(ah[am][2]));
                ah[am][3] = f2tf32(f3); al[am][3] = f2tf32(f3 - __uint_as_float(ah[am][3]));
            }
#pragma unroll
            for (int n = 0; n < 8; n++) {
                int c = wn0 + n * 8 + (lane >> 2);
                float g0 = pB[(kb + (lane & 3)) * SBSTR + c];
                float g1 = pB[(kb + (lane & 3) + 4) * SBSTR + c];
                uint32_t bh0 = f2tf32(g0), bh1 = f2tf32(g1);
                uint32_t bl0 = f2tf32(g0 - __uint_as_float(bh0));
                uint32_t bl1 = f2tf32(g1 - __uint_as_float(bh1));
#pragma unroll
                for (int am = 0; am < 2; am++) {
                    mma8(acc[am][n], al[am][0], al[am][1], al[am][2], al[am][3], bh0, bh1);
                    mma8(acc[am][n], ah[am][0], ah[am][1], ah[am][2], ah[am][3], bl0, bl1);
                    mma8(acc[am][n], ah[am][0], ah[am][1], ah[am][2], ah[am][3], bh0, bh1);
                }
            }
        }
        if (t < 3) {
            asm volatile("cp.async.wait_group 0;" ::: "memory");
        }
        __syncthreads();
    }

    // ---- fused epilogue: stage C tile in smem, then warp-collective chains ----
    float* sC = smem;   // reuse mainloop buffers (all consumers synced above)
#pragma unroll
    for (int am = 0; am < 2; am++) {
        int r = wm0 + am * 16 + (lane >> 2);
#pragma unroll
        for (int n = 0; n < 8; n++) {
            int cidx = wn0 + n * 8 + (lane & 3) * 2;
            sC[r * CSTR + cidx]           = acc[am][n][0];
            sC[r * CSTR + cidx + 1]       = acc[am][n][1];
            sC[(r + 8) * CSTR + cidx]     = acc[am][n][2];
            sC[(r + 8) * CSTR + cidx + 1] = acc[am][n][3];
        }
    }
    __syncthreads();

    int mode = mode_base + blockIdx.y;
    float K = d_K, sq = d_sqrtK;
    const float* ub = (mode == 0) ? d_ub1 : (mode == 1) ? d_ubg1 : d_ubg2;

    for (int rr = 0; rr < 16; rr++) {
        int row = w * 16 + rr;
        int node = r0 + row;
        if (node >= NN) break;
        float v[4];
#pragma unroll
        for (int i = 0; i < 4; i++) v[i] = sC[row * CSTR + lane * 4 + i];

        float P[4];  float p0 = hpoint(v, P, lane, K, sq);
        float G[4];  float g0 = mobius_add_pt(P, p0, ub, G, lane, K, sq);
        float l1[4]; logmap0p(G, g0, l1, lane, sq);

        if (mode == 0) {
            float* o1 = d_la1 + (size_t)node * 128 + lane * 4;
#pragma unroll
            for (int i = 0; i < 4; i++) o1[i] = l1[i];
            float n = nparam[node];
            float v2[4];
#pragma unroll
            for (int i = 0; i < 4; i++) v2[i] = n * l1[i];
            float A2[4]; float a20 = hpoint(v2, A2, lane, K, sq);
            float l2[4]; logmap0p(A2, a20, l2, lane, sq);
            float* o2 = d_la2 + (size_t)node * 128 + lane * 4;
#pragma unroll
            for (int i = 0; i < 4; i++) o2[i] = l2[i];
        } else {
            store_g_h(node, lane, l1);
        }
    }
}

// ---------------- fused SpMM + post chain (fp16 gathers) ----------------
__device__ __forceinline__ void spmm_gather(int row, int lane, float acc[4]) {
    int s = d_rowptr[row];
    int e = d_rowptr[row + 1];
    float4 a = make_float4(0.f, 0.f, 0.f, 0.f);
    int i = s;
    for (; i + 2 <= e; i += 2) {
        int2 p0 = d_epack[i];
        int2 p1 = d_epack[i + 1];
        uint2 q0 = ((const uint2*)(d_gh + (size_t)p0.x * 64))[lane];
        uint2 q1 = ((const uint2*)(d_gh + (size_t)p1.x * 64))[lane];
        float2 g0a = __half22float2(*(__half2*)&q0.x);
        float2 g0b = __half22float2(*(__half2*)&q0.y);
        float2 g1a = __half22float2(*(__half2*)&q1.x);
        float2 g1b = __half22float2(*(__half2*)&q1.y);
        float v0 = __int_as_float(p0.y);
        float v1 = __int_as_float(p1.y);
        a.x = fmaf(v0, g0a.x, fmaf(v1, g1a.x, a.x));
        a.y = fmaf(v0, g0a.y, fmaf(v1, g1a.y, a.y));
        a.z = fmaf(v0, g0b.x, fmaf(v1, g1b.x, a.z));
        a.w = fmaf(v0, g0b.y, fmaf(v1, g1b.y, a.w));
    }
    if (i < e) {
        int2 p0 = d_epack[i];
        uint2 q0 = ((const uint2*)(d_gh + (size_t)p0.x * 64))[lane];
        float2 g0a = __half22float2(*(__half2*)&q0.x);
        float2 g0b = __half22float2(*(__half2*)&q0.y);
        float v0 = __int_as_float(p0.y);
        a.x = fmaf(v0, g0a.x, a.x);
        a.y = fmaf(v0, g0a.y, a.y);
        a.z = fmaf(v0, g0b.x, a.z);
        a.w = fmaf(v0, g0b.y, a.w);
    }
    acc[0] = a.x; acc[1] = a.y; acc[2] = a.z; acc[3] = a.w;
}

__global__ void __launch_bounds__(256) spmm_l1(const float* __restrict__ nparam) {
    int row = blockIdx.x * 8 + (threadIdx.x >> 5);
    int lane = threadIdx.x & 31;
    if (row >= NN) return;
    float K = d_K, sq = d_sqrtK;
    float v[4];
    spmm_gather(row, lane, v);
    float X[4]; float x0 = hpoint(v, X, lane, K, sq);
    float l[4]; logmap0p(X, x0, l, lane, sq);
    float n = 1.0f - nparam[row];
    float v2[4];
#pragma unroll
    for (int i = 0; i < 4; i++) v2[i] = n * l[i];
    float X2[4]; float x20 = hpoint(v2, X2, lane, K, sq);
    float l2[4]; logmap0p(X2, x20, l2, lane, sq);
    const float* a2r = d_la2 + (size_t)row * 128 + lane * 4;
    float w[4];
#pragma unroll
    for (int i = 0; i < 4; i++) w[i] = l2[i] + a2r[i];
    float X3[4]; float x30 = hpoint(w, X3, lane, K, sq);
    float lx[4]; logmap0p(X3, x30, lx, lane, sq);
    float* o = d_lx + (size_t)row * 128 + lane * 4;
#pragma unroll
    for (int i = 0; i < 4; i++) o[i] = lx[i];
}

__global__ void __launch_bounds__(256) spmm_l2() {
    int row = blockIdx.x * 8 + (threadIdx.x >> 5);
    int lane = threadIdx.x & 31;
    if (row >= NN) return;
    float K = d_K, sq = d_sqrtK;
    float v[4];
    spmm_gather(row, lane, v);
    float X[4]; float x0 = hpoint(v, X, lane, K, sq);
    float lx[4]; logmap0p(X, x0, lx, lane, sq);
    float* o = d_lx + (size_t)row * 128 + lane * 4;
#pragma unroll
    for (int i = 0; i < 4; i++) o[i] = lx[i];
}

// ---------------- head ----------------
__global__ void __launch_bounds__(128) head(const int* __restrict__ bidx,
                                            const float* __restrict__ wt,
                                            const float* __restrict__ wt2,
                                            const float* __restrict__ c1w,
                                            const float* __restrict__ c1b,
                                            const float* __restrict__ c2w,
                                            const float* __restrict__ c2b,
                                            const float* __restrict__ cls,
                                            const float* __restrict__ clsb,
                                            float* __restrict__ out) {
    int b = blockIdx.x;
    int d = threadIdx.x;
    __shared__ float sg2[128], sg3[128], sel[100];
    float g2 = 0.0f, g3 = 0.0f;
    const int* bi = bidx + (size_t)b * ML;
    for (int l = 0; l < ML; l++) {
        int idx = bi[l];
        float w1 = c1w[l], w2 = c2w[l];
        g2 = fmaf(w1, d_lx [(size_t)idx * 128 + d], g2);
        g3 = fmaf(w2, d_la1[(size_t)idx * 128 + d], g3);
    }
    sg2[d] = g2; sg3[d] = g3;
    __syncthreads();
    if (d < ML) {
        float s2 = c1b[0], s3 = c2b[0];
        for (int k = 0; k < 128; k++) {
            s2 = fmaf(sg2[k], wt [k * ML + d], s2);
            s3 = fmaf(sg3[k], wt2[k * ML + d], s3);
        }
        sel[d]      = s2;
        sel[ML + d] = s3;
        out[BB + (size_t)b * 100 + d]      = s2;
        out[BB + (size_t)b * 100 + ML + d] = s3;
    }
    __syncthreads();
    if (d == 0) {
        float best = -3.4e38f;
        int bj = 0;
        for (int j = 0; j < 5; j++) {
            float p = clsb[j];
            for (int i = 0; i < 100; i++) p = fmaf(sel[i], cls[i * 5 + j], p);
            if (p > best) { best = p; bj = j; }
        }
        out[b] = (float)bj;
    }
}

// ---------------- launch ----------------
extern "C" void kernel_launch(void* const* d_in, const int* in_sizes, int n_in,
                              void* d_out, int out_size) {
    const float* A1   = (const float*)d_in[0];
    const int*   rows = (const int*)  d_in[1];
    const int*   cols = (const int*)  d_in[2];
    const float* vals = (const float*)d_in[3];
    const int*   bidx = (const int*)  d_in[4];
    const float* rc   = (const float*)d_in[5];
    const float* np   = (const float*)d_in[6];
    const float* Lin1 = (const float*)d_in[7];
    const float* L1b  = (const float*)d_in[8];
    const float* g1w  = (const float*)d_in[9];
    const float* g1b  = (const float*)d_in[10];
    const float* g2w  = (const float*)d_in[11];
    const float* g2b  = (const float*)d_in[12];
    const float* wt   = (const float*)d_in[13];
    const float* wt2  = (const float*)d_in[14];
    const float* c1w  = (const float*)d_in[15];
    const float* c1b  = (const float*)d_in[16];
    const float* c2w  = (const float*)d_in[17];
    const float* c2b  = (const float*)d_in[18];
    const float* cls  = (const float*)d_in[19];
    const float* clsb = (const float*)d_in[20];
    float* out = (float*)d_out;

    float* p_la;    cudaGetSymbolAddress((void**)&p_la,    d_la);
    float* p_lx;    cudaGetSymbolAddress((void**)&p_lx,    d_lx);
    float* p_wcat;  cudaGetSymbolAddress((void**)&p_wcat,  d_Wcat);

    cudaFuncSetAttribute(mma_gemm, cudaFuncAttributeMaxDynamicSharedMemorySize, SMEM_BYTES);

    k0<<<1, 1>>>(rc, L1b, g1b, g2b);
    prep_wcat<<<128, 256>>>(Lin1, g1w);
    k1<<<12500, 256>>>(A1);
    // gemm1 + fused t1/p1 chains (modes 0,1)
    mma_gemm<<<dim3(782, 2), 256, SMEM_BYTES>>>(p_la, p_wcat, np, 0, 256);  // #4 profiled

    // CSR build (reused by both aggregation passes)
    zero_cnt<<<(NPAD + 255) / 256, 256>>>();
    hist<<<(EE + 255) / 256, 256>>>(rows);
    scan1<<<98, 1024>>>();
    scan2<<<1, 128>>>();
    scan3<<<(NPAD + 255) / 256, 256>>>();
    scatter<<<(EE + 255) / 256, 256>>>(rows, cols, vals);

    spmm_l1<<<12500, 256>>>(np);
    // gemm2 + fused q chain (mode 2)
    mma_gemm<<<dim3(782, 1), 256, SMEM_BYTES>>>(p_lx, g2w, np, 2, 128);
    spmm_l2<<<12500, 256>>>();
    head<<<BB, 128>>>(bidx, wt, wt2, c1w, c1b, c2w, c2b, cls, clsb, out);
}

// round 13
// speedup vs baseline: 1.1808x; 1.1808x over previous
#include <cuda_runtime.h>
#include <cuda_fp16.h>
#include <math.h>
#include <stdint.h>

#define NN 100000
#define NROWS 100096   // 782 * 128
#define EE 1600000
#define BB 4096
#define ML 50
#define NPAD 100352    // 98 * 1024

#define MIN_NORM 1e-15f
#define EPSC 1e-7f
#define MAX_NORMC 1000000.0f

// ---------------- persistent scratch ----------------
__device__ float d_K, d_sqrtK;
__device__ float d_ub1[128], d_ubg1[128], d_ubg2[128];
__device__ float d_la  [(size_t)NROWS * 128];
__device__ float d_t1p1[(size_t)NROWS * 256];
__device__ __half2 d_la1h[(size_t)NN * 64];  // fp16 logmap0(a1) (head gathers only)
__device__ float d_la2 [(size_t)NN * 128];
__device__ __half2 d_gh [(size_t)NN * 64];   // fp16 pre-aggregation tangents
__device__ float d_lx  [(size_t)NROWS * 128];
__device__ float d_Wcat[128 * 256];

// CSR scratch
__device__ int  d_cnt[NPAD];
__device__ int  d_rowptr[NPAD];
__device__ int  d_woff[NN];
__device__ int  d_bsum[98];
__device__ int  d_bscan[98];
__device__ int2 d_epack[EE];

// ---------------- warp helpers ----------------
__device__ __forceinline__ float wsum(float v) {
#pragma unroll
    for (int o = 16; o > 0; o >>= 1) v += __shfl_xor_sync(0xffffffffu, v, o);
    return v;
}

__device__ __forceinline__ float sdot(const float* a, const float* b, int lane) {
    float s = a[1] * b[1] + a[2] * b[2] + a[3] * b[3];
    if (lane != 0) s += a[0] * b[0];
    return wsum(s);
}

__device__ __forceinline__ float hpoint(const float in[4], float out[4], int lane,
                                        float K, float sqrtK) {
    float ss = sdot(in, in, lane);
    float xn = fmaxf(sqrtf(ss), MIN_NORM);
    float th = xn / sqrtK;
    float s  = sqrtK * sinhf(th) / xn;
#pragma unroll
    for (int i = 0; i < 4; i++) out[i] = s * in[i];
    float ss2 = sdot(out, out, lane);
    float p0  = sqrtf(fmaxf(K + ss2, EPSC));
    if (lane == 0) out[0] = p0;
    return p0;
}

__device__ __forceinline__ void logmap0p(const float p[4], float p0, float out[4],
                                         int lane, float sqrtK) {
    float ssp = sdot(p, p, lane);
    float yn  = fmaxf(sqrtf(ssp), MIN_NORM);
    float t   = fmaxf(p0 / sqrtK, 1.0f + EPSC);
    float sc  = sqrtK * acoshf(t) / yn;
#pragma unroll
    for (int i = 0; i < 4; i++) out[i] = sc * p[i];
    if (lane == 0) out[0] = 0.0f;
}

__device__ __forceinline__ float mobius_add_pt(const float p[4], float p0,
                                               const float* __restrict__ u,
                                               float out[4], int lane,
                                               float K, float sqrtK) {
    float uv[4];
#pragma unroll
    for (int i = 0; i < 4; i++) uv[i] = u[lane * 4 + i];
    float ssp   = sdot(p, p, lane);
    float yn    = fmaxf(sqrtf(ssp), MIN_NORM);
    float du    = sdot(p, uv, lane);
    float alpha = du / (yn * sqrtK);
    float beta  = alpha * (sqrtK - p0) / yn;
    float w[4];
#pragma unroll
    for (int i = 0; i < 4; i++) w[i] = uv[i] - beta * p[i];
    float ux = sdot(p, w, lane);
    float w0 = ux / fmaxf(p0, EPSC);
    float wss   = sdot(w, w, lane);
    float md    = wss - w0 * w0;
    float normu = fminf(sqrtf(fmaxf(md, EPSC)), MAX_NORMC);
    float th    = fmaxf(normu / sqrtK, MIN_NORM);
    float ch    = coshf(th);
    float sh    = sinhf(th) / th;
#pragma unroll
    for (int i = 0; i < 4; i++) out[i] = ch * p[i] + sh * w[i];
    float rss = sdot(out, out, lane);
    float q0  = sqrtf(fmaxf(K + rss, EPSC));
    if (lane == 0) out[0] = q0;
    return q0;
}

__device__ __forceinline__ void store_h(__half2* base, int row, int lane, const float v[4]) {
    __half2* p = base + (size_t)row * 64 + lane * 2;
    p[0] = __floats2half2_rn(v[0], v[1]);
    p[1] = __floats2half2_rn(v[2], v[3]);
}

// ---------------- K0 ----------------
__device__ void bias_u(const float* b, float* u, float K, float sqrtK) {
    float ss = 0.0f;
    for (int i = 1; i < 128; i++) ss += b[i] * b[i];
    float xn = fmaxf(sqrtf(ss), MIN_NORM);
    float th = xn / sqrtK;
    float s  = sqrtK * sinhf(th) / xn;
    float y[128];
    float ss2 = 0.0f;
    for (int i = 1; i < 128; i++) { y[i] = s * b[i]; ss2 += y[i] * y[i]; }
    float x0 = sqrtf(fmaxf(K + ss2, EPSC));
    float yn = fmaxf(sqrtf(ss2), MIN_NORM);
    float t  = fmaxf(x0 / sqrtK, 1.0f + EPSC);
    float sc = sqrtK * acoshf(t) / yn;
    u[0] = 0.0f;
    for (int i = 1; i < 128; i++) u[i] = sc * y[i];
}

__global__ void k0(const float* __restrict__ rc, const float* __restrict__ b1,
                   const float* __restrict__ bg1, const float* __restrict__ bg2) {
    float c = log1pf(expf(rc[0])) + 1e-5f;
    float K = 1.0f / c, sq = sqrtf(K);
    d_K = K; d_sqrtK = sq;
    bias_u(b1,  d_ub1,  K, sq);
    bias_u(bg1, d_ubg1, K, sq);
    bias_u(bg2, d_ubg2, K, sq);
}

__global__ void prep_wcat(const float* __restrict__ Lin1, const float* __restrict__ g1w) {
    int j = blockIdx.x * 256 + threadIdx.x;
    int k = j >> 8, col = j & 255;
    d_Wcat[j] = (col < 128) ? Lin1[(k + 1) * 128 + col]
                            : g1w[(k + 1) * 128 + (col - 128)];
}

// ---------------- CSR build ----------------
__global__ void zero_cnt() {
    int i = blockIdx.x * 256 + threadIdx.x;
    if (i < NPAD) d_cnt[i] = 0;
}

__global__ void hist(const int* __restrict__ rows) {
    int e = blockIdx.x * 256 + threadIdx.x;
    if (e < EE) atomicAdd(&d_cnt[rows[e]], 1);
}

__global__ void __launch_bounds__(1024) scan1() {
    __shared__ int sh[1024];
    int t = threadIdx.x;
    int i = blockIdx.x * 1024 + t;
    int v = d_cnt[i];
    sh[t] = v;
    __syncthreads();
#pragma unroll
    for (int off = 1; off < 1024; off <<= 1) {
        int x = (t >= off) ? sh[t - off] : 0;
        __syncthreads();
        sh[t] += x;
        __syncthreads();
    }
    d_rowptr[i] = sh[t] - v;
    if (t == 1023) d_bsum[blockIdx.x] = sh[1023];
}

__global__ void __launch_bounds__(128) scan2() {
    __shared__ int sh[128];
    int t = threadIdx.x;
    int v = (t < 98) ? d_bsum[t] : 0;
    sh[t] = v;
    __syncthreads();
#pragma unroll
    for (int off = 1; off < 128; off <<= 1) {
        int x = (t >= off) ? sh[t - off] : 0;
        __syncthreads();
        sh[t] += x;
        __syncthreads();
    }
    if (t < 98) d_bscan[t] = sh[t] - v;
}

__global__ void scan3() {
    int i = blockIdx.x * 256 + threadIdx.x;
    if (i < NPAD) {
        int v = d_rowptr[i] + d_bscan[i >> 10];
        d_rowptr[i] = v;
        if (i < NN) d_woff[i] = v;
    }
}

__global__ void scatter(const int* __restrict__ rows, const int* __restrict__ cols,
                        const float* __restrict__ vals) {
    int e = blockIdx.x * 256 + threadIdx.x;
    if (e < EE) {
        int r = rows[e];
        int pos = atomicAdd(&d_woff[r], 1);
        d_epack[pos] = make_int2(cols[e], __float_as_int(vals[e]));
    }
}

// ---------------- K1 ----------------
__global__ void __launch_bounds__(256) k1(const float* __restrict__ A1) {
    int node = blockIdx.x * 8 + (threadIdx.x >> 5);
    int lane = threadIdx.x & 31;
    float K = d_K, sq = d_sqrtK;
    const float* row = A1 + (size_t)node * 129 + 1;
    float x[4];
#pragma unroll
    for (int i = 0; i < 4; i++) x[i] = row[lane * 4 + i];
    float ss = wsum(x[0]*x[0] + x[1]*x[1] + x[2]*x[2] + x[3]*x[3]);
    float xn = fmaxf(sqrtf(ss), MIN_NORM);
    float th = xn / sq;
    float s  = sq * sinhf(th) / xn;
    float y[4];
#pragma unroll
    for (int i = 0; i < 4; i++) y[i] = s * x[i];
    float ss2 = wsum(y[0]*y[0] + y[1]*y[1] + y[2]*y[2] + y[3]*y[3]);
    float x0 = sqrtf(fmaxf(K + ss2, EPSC));
    float yn = fmaxf(sqrtf(ss2), MIN_NORM);
    float t  = fmaxf(x0 / sq, 1.0f + EPSC);
    float sc = sq * acoshf(t) / yn;
    float* o = d_la + (size_t)node * 128 + lane * 4;
#pragma unroll
    for (int i = 0; i < 4; i++) o[i] = sc * y[i];
}

// ---------------- TF32 MMA GEMM (R5/R8 structure: BK=32, inline splits) --------
#define SASTR 36
#define SBSTR 136
#define SA_FL (128 * SASTR)   // 4608 floats per buffer
#define SB_FL (32 * SBSTR)    // 4352 floats per buffer
#define SMEM_BYTES ((2 * (SA_FL + SB_FL)) * 4)   // 71680

__device__ __forceinline__ uint32_t f2tf32(float f) {
    uint32_t r;
    asm("cvt.rna.tf32.f32 %0, %1;" : "=r"(r) : "f"(f));
    return r;
}

__device__ __forceinline__ void mma8(float c[4], uint32_t a0, uint32_t a1,
                                     uint32_t a2, uint32_t a3,
                                     uint32_t b0, uint32_t b1) {
    asm volatile(
        "mma.sync.aligned.m16n8k8.row.col.f32.tf32.tf32.f32 "
        "{%0,%1,%2,%3}, {%4,%5,%6,%7}, {%8,%9}, {%0,%1,%2,%3};"
        : "+f"(c[0]), "+f"(c[1]), "+f"(c[2]), "+f"(c[3])
        : "r"(a0), "r"(a1), "r"(a2), "r"(a3), "r"(b0), "r"(b1));
}

__device__ __forceinline__ void cpasync16(uint32_t saddr, const void* gptr) {
    asm volatile("cp.async.ca.shared.global [%0], [%1], 16;" :: "r"(saddr), "l"(gptr));
}

__global__ void __launch_bounds__(256, 2) mma_gemm(const float* __restrict__ A,
                                                   const float* __restrict__ W,
                                                   float* __restrict__ C, int N) {
    extern __shared__ float smem[];
    float* sA[2] = { smem, smem + SA_FL };
    float* sB[2] = { smem + 2 * SA_FL, smem + 2 * SA_FL + SB_FL };

    int tid  = threadIdx.x;
    int lane = tid & 31;
    int w    = tid >> 5;
    int wm0  = (w & 3) * 32;
    int wn0  = (w >> 2) * 64;
    int r0   = blockIdx.x * 128;
    int n0   = blockIdx.y * 128;

    int a_row = tid >> 1, a_half = (tid & 1) * 16;
    int b_k   = tid >> 3, b_seg  = (tid & 7) * 16;

    const float* Agp = A + (size_t)(r0 + a_row) * 128 + a_half;
    const float* Wgp = W + (size_t)b_k * N + n0 + b_seg;

    auto load_tile = [&](int buf, int k0) {
        uint32_t sa = (uint32_t)__cvta_generic_to_shared(sA[buf] + a_row * SASTR + a_half);
        const float* ag = Agp + k0;
#pragma unroll
        for (int i = 0; i < 4; i++) cpasync16(sa + i * 16, ag + i * 4);
        uint32_t sb = (uint32_t)__cvta_generic_to_shared(sB[buf] + b_k * SBSTR + b_seg);
        const float* bg = Wgp + (size_t)k0 * N;
#pragma unroll
        for (int i = 0; i < 4; i++) cpasync16(sb + i * 16, bg + i * 4);
        asm volatile("cp.async.commit_group;");
    };

    float acc[2][8][4];
#pragma unroll
    for (int am = 0; am < 2; am++)
#pragma unroll
        for (int n = 0; n < 8; n++)
#pragma unroll
            for (int i = 0; i < 4; i++) acc[am][n][i] = 0.0f;

    load_tile(0, 0);
    asm volatile("cp.async.wait_group 0;" ::: "memory");
    __syncthreads();

#pragma unroll
    for (int t = 0; t < 4; t++) {
        int cur = t & 1, nxt = cur ^ 1;
        if (t < 3) load_tile(nxt, (t + 1) * 32);

        const float* pA = sA[cur];
        const float* pB = sB[cur];
#pragma unroll
        for (int ks = 0; ks < 4; ks++) {
            int kb = ks * 8;
            uint32_t ah[2][4], al[2][4];
#pragma unroll
            for (int am = 0; am < 2; am++) {
                int m = wm0 + am * 16 + (lane >> 2);
                int c = kb + (lane & 3);
                float f0 = pA[m * SASTR + c];
                float f1 = pA[(m + 8) * SASTR + c];
                float f2 = pA[m * SASTR + c + 4];
                float f3 = pA[(m + 8) * SASTR + c + 4];
                ah[am][0] = f2tf32(f0); al[am][0] = f2tf32(f0 - __uint_as_float(ah[am][0]));
                ah[am][1] = f2tf32(f1); al[am][1] = f2tf32(f1 - __uint_as_float(ah[am][1]));
                ah[am][2] = f2tf32(f2); al[am][2] = f2tf32(f2 - __uint_as_float(ah[am][2]));
                ah[am][3] = f2tf32(f3); al[am][3] = f2tf32(f3 - __uint_as_float(ah[am][3]));
            }
#pragma unroll
            for (int n = 0; n < 8; n++) {
                int c = wn0 + n * 8 + (lane >> 2);
                float g0 = pB[(kb + (lane & 3)) * SBSTR + c];
                float g1 = pB[(kb + (lane & 3) + 4) * SBSTR + c];
                uint32_t bh0 = f2tf32(g0), bh1 = f2tf32(g1);
                uint32_t bl0 = f2tf32(g0 - __uint_as_float(bh0));
                uint32_t bl1 = f2tf32(g1 - __uint_as_float(bh1));
#pragma unroll
                for (int am = 0; am < 2; am++) {
                    mma8(acc[am][n], al[am][0], al[am][1], al[am][2], al[am][3], bh0, bh1);
                    mma8(acc[am][n], ah[am][0], ah[am][1], ah[am][2], ah[am][3], bl0, bl1);
                    mma8(acc[am][n], ah[am][0], ah[am][1], ah[am][2], ah[am][3], bh0, bh1);
                }
            }
        }
        if (t < 3) {
            asm volatile("cp.async.wait_group 0;" ::: "memory");
        }
        __syncthreads();
    }

#pragma unroll
    for (int am = 0; am < 2; am++) {
        int mrow = r0 + wm0 + am * 16 + (lane >> 2);
#pragma unroll
        for (int n = 0; n < 8; n++) {
            int col = n0 + wn0 + n * 8 + (lane & 3) * 2;
            float2 v0 = make_float2(acc[am][n][0], acc[am][n][1]);
            float2 v1 = make_float2(acc[am][n][2], acc[am][n][3]);
            *(float2*)(C + (size_t)mrow * N + col)       = v0;
            *(float2*)(C + (size_t)(mrow + 8) * N + col) = v1;
        }
    }
}

// ---------------- K3 ----------------
__global__ void __launch_bounds__(256) k3(const float* __restrict__ nparam) {
    int node = blockIdx.x * 8 + (threadIdx.x >> 5);
    int lane = threadIdx.x & 31;
    float K = d_K, sq = d_sqrtK;
    const float* tr = d_t1p1 + (size_t)node * 256;
    float t[4], p[4];
#pragma unroll
    for (int i = 0; i < 4; i++) { t[i] = tr[lane * 4 + i]; p[i] = tr[128 + lane * 4 + i]; }

    float P[4];  float p0 = hpoint(t, P, lane, K, sq);
    float Aa[4]; float a0 = mobius_add_pt(P, p0, d_ub1, Aa, lane, K, sq);
    float l1[4]; logmap0p(Aa, a0, l1, lane, sq);
    store_h(d_la1h, node, lane, l1);

    float n = nparam[node];
    float v2[4];
#pragma unroll
    for (int i = 0; i < 4; i++) v2[i] = n * l1[i];
    float A2[4]; float a20 = hpoint(v2, A2, lane, K, sq);
    float l2[4]; logmap0p(A2, a20, l2, lane, sq);
    float* o2 = d_la2 + (size_t)node * 128 + lane * 4;
#pragma unroll
    for (int i = 0; i < 4; i++) o2[i] = l2[i];

    float Pg[4]; float pg0 = hpoint(p, Pg, lane, K, sq);
    float G[4];  float g0  = mobius_add_pt(Pg, pg0, d_ubg1, G, lane, K, sq);
    float lg[4]; logmap0p(G, g0, lg, lane, sq);
    store_h(d_gh, node, lane, lg);
}

// ---------------- fused SpMM + post chain (fp16 gathers, 4-wide MLP) ------------
__device__ __forceinline__ void edge_fma(float4& a, int2 p) {
    uint2 q = ((const uint2*)(d_gh + (size_t)p.x * 64))[threadIdx.x & 31];
    float2 ga = __half22float2(*(__half2*)&q.x);
    float2 gb = __half22float2(*(__half2*)&q.y);
    float v = __int_as_float(p.y);
    a.x = fmaf(v, ga.x, a.x);
    a.y = fmaf(v, ga.y, a.y);
    a.z = fmaf(v, gb.x, a.z);
    a.w = fmaf(v, gb.y, a.w);
}

__device__ __forceinline__ void spmm_gather(int row, int lane, float acc[4]) {
    int s = d_rowptr[row];
    int e = d_rowptr[row + 1];
    float4 a = make_float4(0.f, 0.f, 0.f, 0.f);
    int i = s;
    for (; i + 4 <= e; i += 4) {
        int2 p0 = d_epack[i];
        int2 p1 = d_epack[i + 1];
        int2 p2 = d_epack[i + 2];
        int2 p3 = d_epack[i + 3];
        uint2 q0 = ((const uint2*)(d_gh + (size_t)p0.x * 64))[lane];
        uint2 q1 = ((const uint2*)(d_gh + (size_t)p1.x * 64))[lane];
        uint2 q2 = ((const uint2*)(d_gh + (size_t)p2.x * 64))[lane];
        uint2 q3 = ((const uint2*)(d_gh + (size_t)p3.x * 64))[lane];
        float v0 = __int_as_float(p0.y), v1 = __int_as_float(p1.y);
        float v2 = __int_as_float(p2.y), v3 = __int_as_float(p3.y);
        float2 g0a = __half22float2(*(__half2*)&q0.x), g0b = __half22float2(*(__half2*)&q0.y);
        float2 g1a = __half22float2(*(__half2*)&q1.x), g1b = __half22float2(*(__half2*)&q1.y);
        float2 g2a = __half22float2(*(__half2*)&q2.x), g2b = __half22float2(*(__half2*)&q2.y);
        float2 g3a = __half22float2(*(__half2*)&q3.x), g3b = __half22float2(*(__half2*)&q3.y);
        a.x = fmaf(v0, g0a.x, fmaf(v1, g1a.x, fmaf(v2, g2a.x, fmaf(v3, g3a.x, a.x))));
        a.y = fmaf(v0, g0a.y, fmaf(v1, g1a.y, fmaf(v2, g2a.y, fmaf(v3, g3a.y, a.y))));
        a.z = fmaf(v0, g0b.x, fmaf(v1, g1b.x, fmaf(v2, g2b.x, fmaf(v3, g3b.x, a.z))));
        a.w = fmaf(v0, g0b.y, fmaf(v1, g1b.y, fmaf(v2, g2b.y, fmaf(v3, g3b.y, a.w))));
    }
    for (; i < e; i++) edge_fma(a, d_epack[i]);
    acc[0] = a.x; acc[1] = a.y; acc[2] = a.z; acc[3] = a.w;
}

__global__ void __launch_bounds__(256) spmm_l1(const float* __restrict__ nparam) {
    int row = blockIdx.x * 8 + (threadIdx.x >> 5);
    int lane = threadIdx.x & 31;
    if (row >= NN) return;
    float K = d_K, sq = d_sqrtK;
    float v[4];
    spmm_gather(row, lane, v);
    float X[4]; float x0 = hpoint(v, X, lane, K, sq);
    float l[4]; logmap0p(X, x0, l, lane, sq);
    float n = 1.0f - nparam[row];
    float v2[4];
#pragma unroll
    for (int i = 0; i < 4; i++) v2[i] = n * l[i];
    float X2[4]; float x20 = hpoint(v2, X2, lane, K, sq);
    float l2[4]; logmap0p(X2, x20, l2, lane, sq);
    const float* a2r = d_la2 + (size_t)row * 128 + lane * 4;
    float w[4];
#pragma unroll
    for (int i = 0; i < 4; i++) w[i] = l2[i] + a2r[i];
    float X3[4]; float x30 = hpoint(w, X3, lane, K, sq);
    float lx[4]; logmap0p(X3, x30, lx, lane, sq);
    float* o = d_lx + (size_t)row * 128 + lane * 4;
#pragma unroll
    for (int i = 0; i < 4; i++) o[i] = lx[i];
}

__global__ void __launch_bounds__(256) spmm_l2() {
    int row = blockIdx.x * 8 + (threadIdx.x >> 5);
    int lane = threadIdx.x & 31;
    if (row >= NN) return;
    float K = d_K, sq = d_sqrtK;
    float v[4];
    spmm_gather(row, lane, v);
    float X[4]; float x0 = hpoint(v, X, lane, K, sq);
    float lx[4]; logmap0p(X, x0, lx, lane, sq);
    float* o = d_lx + (size_t)row * 128 + lane * 4;
#pragma unroll
    for (int i = 0; i < 4; i++) o[i] = lx[i];
}

// ---------------- K9 ----------------
__global__ void __launch_bounds__(256) k9() {
    int node = blockIdx.x * 8 + (threadIdx.x >> 5);
    int lane = threadIdx.x & 31;
    float K = d_K, sq = d_sqrtK;
    const float* qr = d_t1p1 + (size_t)node * 128 + lane * 4;
    float q[4];
#pragma unroll
    for (int i = 0; i < 4; i++) q[i] = qr[i];
    float X[4]; float x0 = hpoint(q, X, lane, K, sq);
    float G[4]; float g0 = mobius_add_pt(X, x0, d_ubg2, G, lane, K, sq);
    float lg[4]; logmap0p(G, g0, lg, lane, sq);
    store_h(d_gh, node, lane, lg);
}

// ---------------- head ----------------
__global__ void __launch_bounds__(128) head(const int* __restrict__ bidx,
                                            const float* __restrict__ wt,
                                            const float* __restrict__ wt2,
                                            const float* __restrict__ c1w,
                                            const float* __restrict__ c1b,
                                            const float* __restrict__ c2w,
                                            const float* __restrict__ c2b,
                                            const float* __restrict__ cls,
                                            const float* __restrict__ clsb,
                                            float* __restrict__ out) {
    int b = blockIdx.x;
    int d = threadIdx.x;
    __shared__ float sg2[128], sg3[128], sel[100];
    float g2 = 0.0f, g3 = 0.0f;
    const int* bi = bidx + (size_t)b * ML;
    const __half* la1 = (const __half*)d_la1h;
    for (int l = 0; l < ML; l++) {
        int idx = bi[l];
        float w1 = c1w[l], w2 = c2w[l];
        g2 = fmaf(w1, d_lx[(size_t)idx * 128 + d], g2);
        g3 = fmaf(w2, __half2float(la1[(size_t)idx * 128 + d]), g3);
    }
    sg2[d] = g2; sg3[d] = g3;
    __syncthreads();
    if (d < ML) {
        float s2 = c1b[0], s3 = c2b[0];
        for (int k = 0; k < 128; k++) {
            s2 = fmaf(sg2[k], wt [k * ML + d], s2);
            s3 = fmaf(sg3[k], wt2[k * ML + d], s3);
        }
        sel[d]      = s2;
        sel[ML + d] = s3;
        out[BB + (size_t)b * 100 + d]      = s2;
        out[BB + (size_t)b * 100 + ML + d] = s3;
    }
    __syncthreads();
    if (d == 0) {
        float best = -3.4e38f;
        int bj = 0;
        for (int j = 0; j < 5; j++) {
            float p = clsb[j];
            for (int i = 0; i < 100; i++) p = fmaf(sel[i], cls[i * 5 + j], p);
            if (p > best) { best = p; bj = j; }
        }
        out[b] = (float)bj;
    }
}

// ---------------- launch ----------------
extern "C" void kernel_launch(void* const* d_in, const int* in_sizes, int n_in,
                              void* d_out, int out_size) {
    const float* A1   = (const float*)d_in[0];
    const int*   rows = (const int*)  d_in[1];
    const int*   cols = (const int*)  d_in[2];
    const float* vals = (const float*)d_in[3];
    const int*   bidx = (const int*)  d_in[4];
    const float* rc   = (const float*)d_in[5];
    const float* np   = (const float*)d_in[6];
    const float* Lin1 = (const float*)d_in[7];
    const float* L1b  = (const float*)d_in[8];
    const float* g1w  = (const float*)d_in[9];
    const float* g1b  = (const float*)d_in[10];
    const float* g2w  = (const float*)d_in[11];
    const float* g2b  = (const float*)d_in[12];
    const float* wt   = (const float*)d_in[13];
    const float* wt2  = (const float*)d_in[14];
    const float* c1w  = (const float*)d_in[15];
    const float* c1b  = (const float*)d_in[16];
    const float* c2w  = (const float*)d_in[17];
    const float* c2b  = (const float*)d_in[18];
    const float* cls  = (const float*)d_in[19];
    const float* clsb = (const float*)d_in[20];
    float* out = (float*)d_out;

    float* p_la;    cudaGetSymbolAddress((void**)&p_la,    d_la);
    float* p_t1p1;  cudaGetSymbolAddress((void**)&p_t1p1,  d_t1p1);
    float* p_lx;    cudaGetSymbolAddress((void**)&p_lx,    d_lx);
    float* p_wcat;  cudaGetSymbolAddress((void**)&p_wcat,  d_Wcat);

    cudaFuncSetAttribute(mma_gemm, cudaFuncAttributeMaxDynamicSharedMemorySize, SMEM_BYTES);

    k0<<<1, 1>>>(rc, L1b, g1b, g2b);
    prep_wcat<<<128, 256>>>(Lin1, g1w);
    k1<<<12500, 256>>>(A1);
    mma_gemm<<<dim3(782, 2), 256, SMEM_BYTES>>>(p_la, p_wcat, p_t1p1, 256);  // #4 profiled
    k3<<<12500, 256>>>(np);

    // CSR build (reused by both aggregation passes)
    zero_cnt<<<(NPAD + 255) / 256, 256>>>();
    hist<<<(EE + 255) / 256, 256>>>(rows);
    scan1<<<98, 1024>>>();
    scan2<<<1, 128>>>();
    scan3<<<(NPAD + 255) / 256, 256>>>();
    scatter<<<(EE + 255) / 256, 256>>>(rows, cols, vals);

    spmm_l1<<<12500, 256>>>(np);
    mma_gemm<<<dim3(782, 1), 256, SMEM_BYTES>>>(p_lx, g2w, p_t1p1, 128);
    k9<<<12500, 256>>>();
    spmm_l2<<<12500, 256>>>();
    head<<<BB, 128>>>(bidx, wt, wt2, c1w, c1b, c2w, c2b, cls, clsb, out);
}

// round 14
// speedup vs baseline: 1.2969x; 1.0984x over previous
#include <cuda_runtime.h>
#include <cuda_fp16.h>
#include <math.h>
#include <stdint.h>

#define NN 100000
#define NROWS 100096   // 782 * 128
#define EE 1600000
#define BB 4096
#define ML 50
#define NPAD 100352    // 98 * 1024

#define MIN_NORM 1e-15f
#define EPSC 1e-7f
#define MAX_NORMC 1000000.0f

// ---------------- persistent scratch ----------------
__device__ float d_K, d_sqrtK;
__device__ float d_ub1[128], d_ubg1[128], d_ubg2[128];
__device__ float d_la  [(size_t)NROWS * 128];
__device__ float d_t1p1[(size_t)NROWS * 256];
__device__ __half2 d_la1h[(size_t)NN * 64];  // fp16 logmap0(a1) (head gathers only)
__device__ float d_la2 [(size_t)NN * 128];
__device__ __half2 d_gh [(size_t)NN * 64];   // fp16 pre-aggregation tangents
__device__ float d_lx  [(size_t)NROWS * 128];   // logmap0(x_1) (gemm2 A input)
__device__ __half2 d_lxh[(size_t)NN * 64];   // fp16 logmap0(x_2) (head gathers only)
__device__ float d_Wcat[128 * 256];

// CSR scratch
__device__ int  d_cnt[NPAD];
__device__ int  d_rowptr[NPAD];
__device__ int  d_woff[NN];
__device__ int  d_bsum[98];
__device__ int  d_bscan[98];
__device__ int2 d_epack[EE];

// ---------------- warp helpers ----------------
__device__ __forceinline__ float wsum(float v) {
#pragma unroll
    for (int o = 16; o > 0; o >>= 1) v += __shfl_xor_sync(0xffffffffu, v, o);
    return v;
}

__device__ __forceinline__ float sdot(const float* a, const float* b, int lane) {
    float s = a[1] * b[1] + a[2] * b[2] + a[3] * b[3];
    if (lane != 0) s += a[0] * b[0];
    return wsum(s);
}

__device__ __forceinline__ float hpoint(const float in[4], float out[4], int lane,
                                        float K, float sqrtK) {
    float ss = sdot(in, in, lane);
    float xn = fmaxf(sqrtf(ss), MIN_NORM);
    float th = xn / sqrtK;
    float s  = sqrtK * sinhf(th) / xn;
#pragma unroll
    for (int i = 0; i < 4; i++) out[i] = s * in[i];
    float ss2 = sdot(out, out, lane);
    float p0  = sqrtf(fmaxf(K + ss2, EPSC));
    if (lane == 0) out[0] = p0;
    return p0;
}

__device__ __forceinline__ void logmap0p(const float p[4], float p0, float out[4],
                                         int lane, float sqrtK) {
    float ssp = sdot(p, p, lane);
    float yn  = fmaxf(sqrtf(ssp), MIN_NORM);
    float t   = fmaxf(p0 / sqrtK, 1.0f + EPSC);
    float sc  = sqrtK * acoshf(t) / yn;
#pragma unroll
    for (int i = 0; i < 4; i++) out[i] = sc * p[i];
    if (lane == 0) out[0] = 0.0f;
}

__device__ __forceinline__ float mobius_add_pt(const float p[4], float p0,
                                               const float* __restrict__ u,
                                               float out[4], int lane,
                                               float K, float sqrtK) {
    float uv[4];
#pragma unroll
    for (int i = 0; i < 4; i++) uv[i] = u[lane * 4 + i];
    float ssp   = sdot(p, p, lane);
    float yn    = fmaxf(sqrtf(ssp), MIN_NORM);
    float du    = sdot(p, uv, lane);
    float alpha = du / (yn * sqrtK);
    float beta  = alpha * (sqrtK - p0) / yn;
    float w[4];
#pragma unroll
    for (int i = 0; i < 4; i++) w[i] = uv[i] - beta * p[i];
    float ux = sdot(p, w, lane);
    float w0 = ux / fmaxf(p0, EPSC);
    float wss   = sdot(w, w, lane);
    float md    = wss - w0 * w0;
    float normu = fminf(sqrtf(fmaxf(md, EPSC)), MAX_NORMC);
    float th    = fmaxf(normu / sqrtK, MIN_NORM);
    float ch    = coshf(th);
    float sh    = sinhf(th) / th;
#pragma unroll
    for (int i = 0; i < 4; i++) out[i] = ch * p[i] + sh * w[i];
    float rss = sdot(out, out, lane);
    float q0  = sqrtf(fmaxf(K + rss, EPSC));
    if (lane == 0) out[0] = q0;
    return q0;
}

__device__ __forceinline__ void store_h(__half2* base, int row, int lane, const float v[4]) {
    __half2* p = base + (size_t)row * 64 + lane * 2;
    p[0] = __floats2half2_rn(v[0], v[1]);
    p[1] = __floats2half2_rn(v[2], v[3]);
}

// ---------------- K0 ----------------
__device__ void bias_u(const float* b, float* u, float K, float sqrtK) {
    float ss = 0.0f;
    for (int i = 1; i < 128; i++) ss += b[i] * b[i];
    float xn = fmaxf(sqrtf(ss), MIN_NORM);
    float th = xn / sqrtK;
    float s  = sqrtK * sinhf(th) / xn;
    float y[128];
    float ss2 = 0.0f;
    for (int i = 1; i < 128; i++) { y[i] = s * b[i]; ss2 += y[i] * y[i]; }
    float x0 = sqrtf(fmaxf(K + ss2, EPSC));
    float yn = fmaxf(sqrtf(ss2), MIN_NORM);
    float t  = fmaxf(x0 / sqrtK, 1.0f + EPSC);
    float sc = sqrtK * acoshf(t) / yn;
    u[0] = 0.0f;
    for (int i = 1; i < 128; i++) u[i] = sc * y[i];
}

__global__ void k0(const float* __restrict__ rc, const float* __restrict__ b1,
                   const float* __restrict__ bg1, const float* __restrict__ bg2) {
    float c = log1pf(expf(rc[0])) + 1e-5f;
    float K = 1.0f / c, sq = sqrtf(K);
    d_K = K; d_sqrtK = sq;
    bias_u(b1,  d_ub1,  K, sq);
    bias_u(bg1, d_ubg1, K, sq);
    bias_u(bg2, d_ubg2, K, sq);
}

__global__ void prep_wcat(const float* __restrict__ Lin1, const float* __restrict__ g1w) {
    int j = blockIdx.x * 256 + threadIdx.x;
    int k = j >> 8, col = j & 255;
    d_Wcat[j] = (col < 128) ? Lin1[(k + 1) * 128 + col]
                            : g1w[(k + 1) * 128 + (col - 128)];
}

// ---------------- CSR build ----------------
// d_cnt is zero at process start (static init) and re-zeroed by scan3 each run.
__global__ void hist(const int* __restrict__ rows) {
    int e = blockIdx.x * 256 + threadIdx.x;
    if (e < EE) atomicAdd(&d_cnt[rows[e]], 1);
}

__global__ void __launch_bounds__(1024) scan1() {
    __shared__ int sh[1024];
    int t = threadIdx.x;
    int i = blockIdx.x * 1024 + t;
    int v = d_cnt[i];
    sh[t] = v;
    __syncthreads();
#pragma unroll
    for (int off = 1; off < 1024; off <<= 1) {
        int x = (t >= off) ? sh[t - off] : 0;
        __syncthreads();
        sh[t] += x;
        __syncthreads();
    }
    d_rowptr[i] = sh[t] - v;
    if (t == 1023) d_bsum[blockIdx.x] = sh[1023];
}

__global__ void __launch_bounds__(128) scan2() {
    __shared__ int sh[128];
    int t = threadIdx.x;
    int v = (t < 98) ? d_bsum[t] : 0;
    sh[t] = v;
    __syncthreads();
#pragma unroll
    for (int off = 1; off < 128; off <<= 1) {
        int x = (t >= off) ? sh[t - off] : 0;
        __syncthreads();
        sh[t] += x;
        __syncthreads();
    }
    if (t < 98) d_bscan[t] = sh[t] - v;
}

__global__ void scan3() {
    int i = blockIdx.x * 256 + threadIdx.x;
    if (i < NPAD) {
        int v = d_rowptr[i] + d_bscan[i >> 10];
        d_rowptr[i] = v;
        if (i < NN) d_woff[i] = v;
        d_cnt[i] = 0;   // reset for next run (replaces zero_cnt kernel)
    }
}

__global__ void scatter(const int* __restrict__ rows, const int* __restrict__ cols,
                        const float* __restrict__ vals) {
    int e = blockIdx.x * 256 + threadIdx.x;
    if (e < EE) {
        int r = rows[e];
        int pos = atomicAdd(&d_woff[r], 1);
        d_epack[pos] = make_int2(cols[e], __float_as_int(vals[e]));
    }
}

// ---------------- K1 ----------------
__global__ void __launch_bounds__(256) k1(const float* __restrict__ A1) {
    int node = blockIdx.x * 8 + (threadIdx.x >> 5);
    int lane = threadIdx.x & 31;
    float K = d_K, sq = d_sqrtK;
    const float* row = A1 + (size_t)node * 129 + 1;
    float x[4];
#pragma unroll
    for (int i = 0; i < 4; i++) x[i] = row[lane * 4 + i];
    float ss = wsum(x[0]*x[0] + x[1]*x[1] + x[2]*x[2] + x[3]*x[3]);
    float xn = fmaxf(sqrtf(ss), MIN_NORM);
    float th = xn / sq;
    float s  = sq * sinhf(th) / xn;
    float y[4];
#pragma unroll
    for (int i = 0; i < 4; i++) y[i] = s * x[i];
    float ss2 = wsum(y[0]*y[0] + y[1]*y[1] + y[2]*y[2] + y[3]*y[3]);
    float x0 = sqrtf(fmaxf(K + ss2, EPSC));
    float yn = fmaxf(sqrtf(ss2), MIN_NORM);
    float t  = fmaxf(x0 / sq, 1.0f + EPSC);
    float sc = sq * acoshf(t) / yn;
    float* o = d_la + (size_t)node * 128 + lane * 4;
#pragma unroll
    for (int i = 0; i < 4; i++) o[i] = sc * y[i];
}

// ---------------- bf16 3-term split MMA GEMM (BK=32, m16n8k16) ----------------
#define SASTR 36
#define SBSTR 136
#define SA_FL (128 * SASTR)   // 4608 floats per buffer
#define SB_FL (32 * SBSTR)    // 4352 floats per buffer
#define SMEM_BYTES ((2 * (SA_FL + SB_FL)) * 4)   // 71680

__device__ __forceinline__ void mma16(float c[4], uint32_t a0, uint32_t a1,
                                      uint32_t a2, uint32_t a3,
                                      uint32_t b0, uint32_t b1) {
    asm volatile(
        "mma.sync.aligned.m16n8k16.row.col.f32.bf16.bf16.f32 "
        "{%0,%1,%2,%3}, {%4,%5,%6,%7}, {%8,%9}, {%0,%1,%2,%3};"
        : "+f"(c[0]), "+f"(c[1]), "+f"(c[2]), "+f"(c[3])
        : "r"(a0), "r"(a1), "r"(a2), "r"(a3), "r"(b0), "r"(b1));
}

// split pair (f_even, f_odd) into bf16x2 hi (truncated) + bf16x2 lo (residual, rn)
// bf16x2 layout: lower 16 bits = even (first k), upper = odd.
__device__ __forceinline__ void split_pair(float fe, float fo, uint32_t& hi, uint32_t& lo) {
    uint32_t ue = __float_as_uint(fe), uo = __float_as_uint(fo);
    asm("prmt.b32 %0, %1, %2, 0x7632;" : "=r"(hi) : "r"(ue), "r"(uo));
    float le = fe - __uint_as_float(ue & 0xFFFF0000u);
    float lf = fo - __uint_as_float(uo & 0xFFFF0000u);
    asm("cvt.rn.bf16x2.f32 %0, %1, %2;" : "=r"(lo) : "f"(lf), "f"(le));
}

__device__ __forceinline__ void cpasync16(uint32_t saddr, const void* gptr) {
    asm volatile("cp.async.ca.shared.global [%0], [%1], 16;" :: "r"(saddr), "l"(gptr));
}

__global__ void __launch_bounds__(256, 2) mma_gemm(const float* __restrict__ A,
                                                   const float* __restrict__ W,
                                                   float* __restrict__ C, int N) {
    extern __shared__ float smem[];
    float* sA[2] = { smem, smem + SA_FL };
    float* sB[2] = { smem + 2 * SA_FL, smem + 2 * SA_FL + SB_FL };

    int tid  = threadIdx.x;
    int lane = tid & 31;
    int w    = tid >> 5;
    int wm0  = (w & 3) * 32;
    int wn0  = (w >> 2) * 64;
    int r0   = blockIdx.x * 128;
    int n0   = blockIdx.y * 128;

    int a_row = tid >> 1, a_half = (tid & 1) * 16;
    int b_k   = tid >> 3, b_seg  = (tid & 7) * 16;

    const float* Agp = A + (size_t)(r0 + a_row) * 128 + a_half;
    const float* Wgp = W + (size_t)b_k * N + n0 + b_seg;

    auto load_tile = [&](int buf, int k0) {
        uint32_t sa = (uint32_t)__cvta_generic_to_shared(sA[buf] + a_row * SASTR + a_half);
        const float* ag = Agp + k0;
#pragma unroll
        for (int i = 0; i < 4; i++) cpasync16(sa + i * 16, ag + i * 4);
        uint32_t sb = (uint32_t)__cvta_generic_to_shared(sB[buf] + b_k * SBSTR + b_seg);
        const float* bg = Wgp + (size_t)k0 * N;
#pragma unroll
        for (int i = 0; i < 4; i++) cpasync16(sb + i * 16, bg + i * 4);
        asm volatile("cp.async.commit_group;");
    };

    float acc[2][8][4];
#pragma unroll
    for (int am = 0; am < 2; am++)
#pragma unroll
        for (int n = 0; n < 8; n++)
#pragma unroll
            for (int i = 0; i < 4; i++) acc[am][n][i] = 0.0f;

    load_tile(0, 0);
    asm volatile("cp.async.wait_group 0;" ::: "memory");
    __syncthreads();

#pragma unroll
    for (int t = 0; t < 4; t++) {
        int cur = t & 1, nxt = cur ^ 1;
        if (t < 3) load_tile(nxt, (t + 1) * 32);

        const float* pA = sA[cur];
        const float* pB = sB[cur];
#pragma unroll
        for (int ks = 0; ks < 2; ks++) {
            int kb = ks * 16;
            int kp = kb + (lane & 3) * 2;
            uint32_t ah[2][4], al[2][4];
#pragma unroll
            for (int am = 0; am < 2; am++) {
                int m = wm0 + am * 16 + (lane >> 2);
                float2 f0 = *(const float2*)&pA[m * SASTR + kp];
                float2 f1 = *(const float2*)&pA[(m + 8) * SASTR + kp];
                float2 f2 = *(const float2*)&pA[m * SASTR + kp + 8];
                float2 f3 = *(const float2*)&pA[(m + 8) * SASTR + kp + 8];
                split_pair(f0.x, f0.y, ah[am][0], al[am][0]);
                split_pair(f1.x, f1.y, ah[am][1], al[am][1]);
                split_pair(f2.x, f2.y, ah[am][2], al[am][2]);
                split_pair(f3.x, f3.y, ah[am][3], al[am][3]);
            }
#pragma unroll
            for (int n = 0; n < 8; n++) {
                int c = wn0 + n * 8 + (lane >> 2);
                float g0 = pB[kp * SBSTR + c];
                float g1 = pB[(kp + 1) * SBSTR + c];
                float g2 = pB[(kp + 8) * SBSTR + c];
                float g3 = pB[(kp + 9) * SBSTR + c];
                uint32_t bh0, bl0, bh1, bl1;
                split_pair(g0, g1, bh0, bl0);
                split_pair(g2, g3, bh1, bl1);
#pragma unroll
                for (int am = 0; am < 2; am++) {
                    mma16(acc[am][n], al[am][0], al[am][1], al[am][2], al[am][3], bh0, bh1);
                    mma16(acc[am][n], ah[am][0], ah[am][1], ah[am][2], ah[am][3], bl0, bl1);
                    mma16(acc[am][n], ah[am][0], ah[am][1], ah[am][2], ah[am][3], bh0, bh1);
                }
            }
        }
        if (t < 3) {
            asm volatile("cp.async.wait_group 0;" ::: "memory");
        }
        __syncthreads();
    }

#pragma unroll
    for (int am = 0; am < 2; am++) {
        int mrow = r0 + wm0 + am * 16 + (lane >> 2);
#pragma unroll
        for (int n = 0; n < 8; n++) {
            int col = n0 + wn0 + n * 8 + (lane & 3) * 2;
            float2 v0 = make_float2(acc[am][n][0], acc[am][n][1]);
            float2 v1 = make_float2(acc[am][n][2], acc[am][n][3]);
            *(float2*)(C + (size_t)mrow * N + col)       = v0;
            *(float2*)(C + (size_t)(mrow + 8) * N + col) = v1;
        }
    }
}

// ---------------- K3 ----------------
__global__ void __launch_bounds__(256) k3(const float* __restrict__ nparam) {
    int node = blockIdx.x * 8 + (threadIdx.x >> 5);
    int lane = threadIdx.x & 31;
    float K = d_K, sq = d_sqrtK;
    const float* tr = d_t1p1 + (size_t)node * 256;
    float t[4], p[4];
#pragma unroll
    for (int i = 0; i < 4; i++) { t[i] = tr[lane * 4 + i]; p[i] = tr[128 + lane * 4 + i]; }

    float P[4];  float p0 = hpoint(t, P, lane, K, sq);
    float Aa[4]; float a0 = mobius_add_pt(P, p0, d_ub1, Aa, lane, K, sq);
    float l1[4]; logmap0p(Aa, a0, l1, lane, sq);
    store_h(d_la1h, node, lane, l1);

    float n = nparam[node];
    float v2[4];
#pragma unroll
    for (int i = 0; i < 4; i++) v2[i] = n * l1[i];
    float A2[4]; float a20 = hpoint(v2, A2, lane, K, sq);
    float l2[4]; logmap0p(A2, a20, l2, lane, sq);
    float* o2 = d_la2 + (size_t)node * 128 + lane * 4;
#pragma unroll
    for (int i = 0; i < 4; i++) o2[i] = l2[i];

    float Pg[4]; float pg0 = hpoint(p, Pg, lane, K, sq);
    float G[4];  float g0  = mobius_add_pt(Pg, pg0, d_ubg1, G, lane, K, sq);
    float lg[4]; logmap0p(G, g0, lg, lane, sq);
    store_h(d_gh, node, lane, lg);
}

// ---------------- fused SpMM + post chain (fp16 gathers, 4-wide MLP) ------------
__device__ __forceinline__ void edge_fma(float4& a, int2 p) {
    uint2 q = ((const uint2*)(d_gh + (size_t)p.x * 64))[threadIdx.x & 31];
    float2 ga = __half22float2(*(__half2*)&q.x);
    float2 gb = __half22float2(*(__half2*)&q.y);
    float v = __int_as_float(p.y);
    a.x = fmaf(v, ga.x, a.x);
    a.y = fmaf(v, ga.y, a.y);
    a.z = fmaf(v, gb.x, a.z);
    a.w = fmaf(v, gb.y, a.w);
}

__device__ __forceinline__ void spmm_gather(int row, int lane, float acc[4]) {
    int s = d_rowptr[row];
    int e = d_rowptr[row + 1];
    float4 a = make_float4(0.f, 0.f, 0.f, 0.f);
    int i = s;
    for (; i + 4 <= e; i += 4) {
        int2 p0 = d_epack[i];
        int2 p1 = d_epack[i + 1];
        int2 p2 = d_epack[i + 2];
        int2 p3 = d_epack[i + 3];
        uint2 q0 = ((const uint2*)(d_gh + (size_t)p0.x * 64))[lane];
        uint2 q1 = ((const uint2*)(d_gh + (size_t)p1.x * 64))[lane];
        uint2 q2 = ((const uint2*)(d_gh + (size_t)p2.x * 64))[lane];
        uint2 q3 = ((const uint2*)(d_gh + (size_t)p3.x * 64))[lane];
        float v0 = __int_as_float(p0.y), v1 = __int_as_float(p1.y);
        float v2 = __int_as_float(p2.y), v3 = __int_as_float(p3.y);
        float2 g0a = __half22float2(*(__half2*)&q0.x), g0b = __half22float2(*(__half2*)&q0.y);
        float2 g1a = __half22float2(*(__half2*)&q1.x), g1b = __half22float2(*(__half2*)&q1.y);
        float2 g2a = __half22float2(*(__half2*)&q2.x), g2b = __half22float2(*(__half2*)&q2.y);
        float2 g3a = __half22float2(*(__half2*)&q3.x), g3b = __half22float2(*(__half2*)&q3.y);
        a.x = fmaf(v0, g0a.x, fmaf(v1, g1a.x, fmaf(v2, g2a.x, fmaf(v3, g3a.x, a.x))));
        a.y = fmaf(v0, g0a.y, fmaf(v1, g1a.y, fmaf(v2, g2a.y, fmaf(v3, g3a.y, a.y))));
        a.z = fmaf(v0, g0b.x, fmaf(v1, g1b.x, fmaf(v2, g2b.x, fmaf(v3, g3b.x, a.z))));
        a.w = fmaf(v0, g0b.y, fmaf(v1, g1b.y, fmaf(v2, g2b.y, fmaf(v3, g3b.y, a.w))));
    }
    for (; i < e; i++) edge_fma(a, d_epack[i]);
    acc[0] = a.x; acc[1] = a.y; acc[2] = a.z; acc[3] = a.w;
}

__global__ void __launch_bounds__(256) spmm_l1(const float* __restrict__ nparam) {
    int row = blockIdx.x * 8 + (threadIdx.x >> 5);
    int lane = threadIdx.x & 31;
    if (row >= NN) return;
    float K = d_K, sq = d_sqrtK;
    float v[4];
    spmm_gather(row, lane, v);
    float X[4]; float x0 = hpoint(v, X, lane, K, sq);
    float l[4]; logmap0p(X, x0, l, lane, sq);
    float n = 1.0f - nparam[row];
    float v2[4];
#pragma unroll
    for (int i = 0; i < 4; i++) v2[i] = n * l[i];
    float X2[4]; float x20 = hpoint(v2, X2, lane, K, sq);
    float l2[4]; logmap0p(X2, x20, l2, lane, sq);
    const float* a2r = d_la2 + (size_t)row * 128 + lane * 4;
    float w[4];
#pragma unroll
    for (int i = 0; i < 4; i++) w[i] = l2[i] + a2r[i];
    float X3[4]; float x30 = hpoint(w, X3, lane, K, sq);
    float lx[4]; logmap0p(X3, x30, lx, lane, sq);
    float* o = d_lx + (size_t)row * 128 + lane * 4;
#pragma unroll
    for (int i = 0; i < 4; i++) o[i] = lx[i];
}

__global__ void __launch_bounds__(256) spmm_l2() {
    int row = blockIdx.x * 8 + (threadIdx.x >> 5);
    int lane = threadIdx.x & 31;
    if (row >= NN) return;
    float K = d_K, sq = d_sqrtK;
    float v[4];
    spmm_gather(row, lane, v);
    float X[4]; float x0 = hpoint(v, X, lane, K, sq);
    float lx[4]; logmap0p(X, x0, lx, lane, sq);
    store_h(d_lxh, row, lane, lx);
}

// ---------------- K9 ----------------
__global__ void __launch_bounds__(256) k9() {
    int node = blockIdx.x * 8 + (threadIdx.x >> 5);
    int lane = threadIdx.x & 31;
    float K = d_K, sq = d_sqrtK;
    const float* qr = d_t1p1 + (size_t)node * 128 + lane * 4;
    float q[4];
#pragma unroll
    for (int i = 0; i < 4; i++) q[i] = qr[i];
    float X[4]; float x0 = hpoint(q, X, lane, K, sq);
    float G[4]; float g0 = mobius_add_pt(X, x0, d_ubg2, G, lane, K, sq);
    float lg[4]; logmap0p(G, g0, lg, lane, sq);
    store_h(d_gh, node, lane, lg);
}

// ---------------- head ----------------
__global__ void __launch_bounds__(128) head(const int* __restrict__ bidx,
                                            const float* __restrict__ wt,
                                            const float* __restrict__ wt2,
                                            const float* __restrict__ c1w,
                                            const float* __restrict__ c1b,
                                            const float* __restrict__ c2w,
                                            const float* __restrict__ c2b,
                                            const float* __restrict__ cls,
                                            const float* __restrict__ clsb,
                                            float* __restrict__ out) {
    int b = blockIdx.x;
    int d = threadIdx.x;
    __shared__ float sg2[128], sg3[128], sel[100];
    float g2 = 0.0f, g3 = 0.0f;
    const int* bi = bidx + (size_t)b * ML;
    const __half* la1 = (const __half*)d_la1h;
    const __half* lxh = (const __half*)d_lxh;
    for (int l = 0; l < ML; l++) {
        int idx = bi[l];
        float w1 = c1w[l], w2 = c2w[l];
        g2 = fmaf(w1, __half2float(lxh[(size_t)idx * 128 + d]), g2);
        g3 = fmaf(w2, __half2float(la1[(size_t)idx * 128 + d]), g3);
    }
    sg2[d] = g2; sg3[d] = g3;
    __syncthreads();
    if (d < ML) {
        float s2 = c1b[0], s3 = c2b[0];
        for (int k = 0; k < 128; k++) {
            s2 = fmaf(sg2[k], wt [k * ML + d], s2);
            s3 = fmaf(sg3[k], wt2[k * ML + d], s3);
        }
        sel[d]      = s2;
        sel[ML + d] = s3;
        out[BB + (size_t)b * 100 + d]      = s2;
        out[BB + (size_t)b * 100 + ML + d] = s3;
    }
    __syncthreads();
    if (d == 0) {
        float best = -3.4e38f;
        int bj = 0;
        for (int j = 0; j < 5; j++) {
            float p = clsb[j];
            for (int i = 0; i < 100; i++) p = fmaf(sel[i], cls[i * 5 + j], p);
            if (p > best) { best = p; bj = j; }
        }
        out[b] = (float)bj;
    }
}

// ---------------- launch ----------------
extern "C" void kernel_launch(void* const* d_in, const int* in_sizes, int n_in,
                              void* d_out, int out_size) {
    const float* A1   = (const float*)d_in[0];
    const int*   rows = (const int*)  d_in[1];
    const int*   cols = (const int*)  d_in[2];
    const float* vals = (const float*)d_in[3];
    const int*   bidx = (const int*)  d_in[4];
    const float* rc   = (const float*)d_in[5];
    const float* np   = (const float*)d_in[6];
    const float* Lin1 = (const float*)d_in[7];
    const float* L1b  = (const float*)d_in[8];
    const float* g1w  = (const float*)d_in[9];
    const float* g1b  = (const float*)d_in[10];
    const float* g2w  = (const float*)d_in[11];
    const float* g2b  = (const float*)d_in[12];
    const float* wt   = (const float*)d_in[13];
    const float* wt2  = (const float*)d_in[14];
    const float* c1w  = (const float*)d_in[15];
    const float* c1b  = (const float*)d_in[16];
    const float* c2w  = (const float*)d_in[17];
    const float* c2b  = (const float*)d_in[18];
    const float* cls  = (const float*)d_in[19];
    const float* clsb = (const float*)d_in[20];
    float* out = (float*)d_out;

    float* p_la;    cudaGetSymbolAddress((void**)&p_la,    d_la);
    float* p_t1p1;  cudaGetSymbolAddress((void**)&p_t1p1,  d_t1p1);
    float* p_lx;    cudaGetSymbolAddress((void**)&p_lx,    d_lx);
    float* p_wcat;  cudaGetSymbolAddress((void**)&p_wcat,  d_Wcat);

    cudaFuncSetAttribute(mma_gemm, cudaFuncAttributeMaxDynamicSharedMemorySize, SMEM_BYTES);

    k0<<<1, 1>>>(rc, L1b, g1b, g2b);
    prep_wcat<<<128, 256>>>(Lin1, g1w);
    k1<<<12500, 256>>>(A1);
    mma_gemm<<<dim3(782, 2), 256, SMEM_BYTES>>>(p_la, p_wcat, p_t1p1, 256);  // #4 profiled
    k3<<<12500, 256>>>(np);

    // CSR build (reused by both aggregation passes)
    hist<<<(EE + 255) / 256, 256>>>(rows);
    scan1<<<98, 1024>>>();
    scan2<<<1, 128>>>();
    scan3<<<(NPAD + 255) / 256, 256>>>();
    scatter<<<(EE + 255) / 256, 256>>>(rows, cols, vals);

    spmm_l1<<<12500, 256>>>(np);
    mma_gemm<<<dim3(782, 1), 256, SMEM_BYTES>>>(p_lx, g2w, p_t1p1, 128);
    k9<<<12500, 256>>>();
    spmm_l2<<<12500, 256>>>();
    head<<<BB, 128>>>(bidx, wt, wt2, c1w, c1b, c2w, c2b, cls, clsb, out);
}

// round 15
// speedup vs baseline: 1.3415x; 1.0344x over previous
#include <cuda_runtime.h>
#include <cuda_fp16.h>
#include <math.h>
#include <stdint.h>

#define NN 100000
#define NROWS 100096   // 782 * 128
#define EE 1600000
#define BB 4096
#define ML 50
#define NPAD 100352    // 98 * 1024

#define MIN_NORM 1e-15f
#define EPSC 1e-7f
#define MAX_NORMC 1000000.0f

// ---------------- persistent scratch ----------------
__device__ float d_K, d_sqrtK;
__device__ float d_ub1[128], d_ubg1[128], d_ubg2[128];
// A operands as packed bf16x2 k-pair planes (hi = truncated, lo = residual)
__device__ uint32_t d_laH[(size_t)NROWS * 64];
__device__ uint32_t d_laL[(size_t)NROWS * 64];
__device__ uint32_t d_lxH[(size_t)NROWS * 64];
__device__ uint32_t d_lxL[(size_t)NROWS * 64];
__device__ float d_t1p1[(size_t)NROWS * 256];
__device__ __half2 d_la1h[(size_t)NN * 64];  // fp16 logmap0(a1) (head)
__device__ float d_la2 [(size_t)NN * 128];
__device__ __half2 d_gh [(size_t)NN * 64];   // fp16 pre-aggregation tangents
__device__ __half2 d_lxh[(size_t)NN * 64];   // fp16 logmap0(x_2) (head)
// W planes: [kpair][col] bf16x2
__device__ uint32_t d_WcatH[64 * 256];
__device__ uint32_t d_WcatL[64 * 256];
__device__ uint32_t d_W2H[64 * 128];
__device__ uint32_t d_W2L[64 * 128];

// CSR scratch
__device__ int  d_cnt[NPAD];
__device__ int  d_rowptr[NPAD];
__device__ int  d_woff[NN];
__device__ int  d_bsum[98];
__device__ int  d_bscan[98];
__device__ int2 d_epack[EE];

// ---------------- bf16 split helpers ----------------
// hi word: [bf16(fo) | bf16(fe)] (lower 16 = even k), truncated
__device__ __forceinline__ uint32_t pack_hi(float fe, float fo) {
    uint32_t ue = __float_as_uint(fe), uo = __float_as_uint(fo);
    uint32_t hi;
    asm("prmt.b32 %0, %1, %2, 0x7632;" : "=r"(hi) : "r"(ue), "r"(uo));
    return hi;
}
__device__ __forceinline__ uint32_t pack_lo(float fe, float fo) {
    float le = fe - __uint_as_float(__float_as_uint(fe) & 0xFFFF0000u);
    float lf = fo - __uint_as_float(__float_as_uint(fo) & 0xFFFF0000u);
    uint32_t lo;
    asm("cvt.rn.bf16x2.f32 %0, %1, %2;" : "=r"(lo) : "f"(lf), "f"(le));
    return lo;
}

// ---------------- warp helpers ----------------
__device__ __forceinline__ float wsum(float v) {
#pragma unroll
    for (int o = 16; o > 0; o >>= 1) v += __shfl_xor_sync(0xffffffffu, v, o);
    return v;
}

__device__ __forceinline__ float sdot(const float* a, const float* b, int lane) {
    float s = a[1] * b[1] + a[2] * b[2] + a[3] * b[3];
    if (lane != 0) s += a[0] * b[0];
    return wsum(s);
}

__device__ __forceinline__ float hpoint(const float in[4], float out[4], int lane,
                                        float K, float sqrtK) {
    float ss = sdot(in, in, lane);
    float xn = fmaxf(sqrtf(ss), MIN_NORM);
    float th = xn / sqrtK;
    float s  = sqrtK * sinhf(th) / xn;
#pragma unroll
    for (int i = 0; i < 4; i++) out[i] = s * in[i];
    float ss2 = sdot(out, out, lane);
    float p0  = sqrtf(fmaxf(K + ss2, EPSC));
    if (lane == 0) out[0] = p0;
    return p0;
}

__device__ __forceinline__ void logmap0p(const float p[4], float p0, float out[4],
                                         int lane, float sqrtK) {
    float ssp = sdot(p, p, lane);
    float yn  = fmaxf(sqrtf(ssp), MIN_NORM);
    float t   = fmaxf(p0 / sqrtK, 1.0f + EPSC);
    float sc  = sqrtK * acoshf(t) / yn;
#pragma unroll
    for (int i = 0; i < 4; i++) out[i] = sc * p[i];
    if (lane == 0) out[0] = 0.0f;
}

__device__ __forceinline__ float mobius_add_pt(const float p[4], float p0,
                                               const float* __restrict__ u,
                                               float out[4], int lane,
                                               float K, float sqrtK) {
    float uv[4];
#pragma unroll
    for (int i = 0; i < 4; i++) uv[i] = u[lane * 4 + i];
    float ssp   = sdot(p, p, lane);
    float yn    = fmaxf(sqrtf(ssp), MIN_NORM);
    float du    = sdot(p, uv, lane);
    float alpha = du / (yn * sqrtK);
    float beta  = alpha * (sqrtK - p0) / yn;
    float w[4];
#pragma unroll
    for (int i = 0; i < 4; i++) w[i] = uv[i] - beta * p[i];
    float ux = sdot(p, w, lane);
    float w0 = ux / fmaxf(p0, EPSC);
    float wss   = sdot(w, w, lane);
    float md    = wss - w0 * w0;
    float normu = fminf(sqrtf(fmaxf(md, EPSC)), MAX_NORMC);
    float th    = fmaxf(normu / sqrtK, MIN_NORM);
    float ch    = coshf(th);
    float sh    = sinhf(th) / th;
#pragma unroll
    for (int i = 0; i < 4; i++) out[i] = ch * p[i] + sh * w[i];
    float rss = sdot(out, out, lane);
    float q0  = sqrtf(fmaxf(K + rss, EPSC));
    if (lane == 0) out[0] = q0;
    return q0;
}

__device__ __forceinline__ void store_h(__half2* base, int row, int lane, const float v[4]) {
    __half2* p = base + (size_t)row * 64 + lane * 2;
    p[0] = __floats2half2_rn(v[0], v[1]);
    p[1] = __floats2half2_rn(v[2], v[3]);
}

__device__ __forceinline__ void store_split(uint32_t* H, uint32_t* L, int row, int lane,
                                            const float v[4]) {
    size_t o = (size_t)row * 64 + lane * 2;
    H[o]     = pack_hi(v[0], v[1]);
    H[o + 1] = pack_hi(v[2], v[3]);
    L[o]     = pack_lo(v[0], v[1]);
    L[o + 1] = pack_lo(v[2], v[3]);
}

// ---------------- K0 ----------------
__device__ void bias_u(const float* b, float* u, float K, float sqrtK) {
    float ss = 0.0f;
    for (int i = 1; i < 128; i++) ss += b[i] * b[i];
    float xn = fmaxf(sqrtf(ss), MIN_NORM);
    float th = xn / sqrtK;
    float s  = sqrtK * sinhf(th) / xn;
    float y[128];
    float ss2 = 0.0f;
    for (int i = 1; i < 128; i++) { y[i] = s * b[i]; ss2 += y[i] * y[i]; }
    float x0 = sqrtf(fmaxf(K + ss2, EPSC));
    float yn = fmaxf(sqrtf(ss2), MIN_NORM);
    float t  = fmaxf(x0 / sqrtK, 1.0f + EPSC);
    float sc = sqrtK * acoshf(t) / yn;
    u[0] = 0.0f;
    for (int i = 1; i < 128; i++) u[i] = sc * y[i];
}

__global__ void k0(const float* __restrict__ rc, const float* __restrict__ b1,
                   const float* __restrict__ bg1, const float* __restrict__ bg2) {
    float c = log1pf(expf(rc[0])) + 1e-5f;
    float K = 1.0f / c, sq = sqrtf(K);
    d_K = K; d_sqrtK = sq;
    bias_u(b1,  d_ub1,  K, sq);
    bias_u(bg1, d_ubg1, K, sq);
    bias_u(bg2, d_ubg2, K, sq);
}

// ---------------- weight prep: packed bf16x2 hi/lo planes ----------------
__device__ __forceinline__ float wcat_val(const float* __restrict__ Lin1,
                                          const float* __restrict__ g1w, int k, int c) {
    return (c < 128) ? Lin1[(k + 1) * 128 + c] : g1w[(k + 1) * 128 + (c - 128)];
}

__global__ void prep_wcat(const float* __restrict__ Lin1, const float* __restrict__ g1w) {
    int j = blockIdx.x * 256 + threadIdx.x;   // 0..16383
    int kp = j >> 8, c = j & 255;
    float fe = wcat_val(Lin1, g1w, 2 * kp, c);
    float fo = wcat_val(Lin1, g1w, 2 * kp + 1, c);
    d_WcatH[j] = pack_hi(fe, fo);
    d_WcatL[j] = pack_lo(fe, fo);
}

__global__ void prep_w2(const float* __restrict__ g2w) {
    int j = blockIdx.x * 256 + threadIdx.x;   // 0..8191
    int kp = j >> 7, c = j & 127;
    float fe = g2w[(2 * kp) * 128 + c];
    float fo = g2w[(2 * kp + 1) * 128 + c];
    d_W2H[j] = pack_hi(fe, fo);
    d_W2L[j] = pack_lo(fe, fo);
}

// ---------------- CSR build ----------------
__global__ void hist(const int* __restrict__ rows) {
    int e = blockIdx.x * 256 + threadIdx.x;
    if (e < EE) atomicAdd(&d_cnt[rows[e]], 1);
}

__global__ void __launch_bounds__(1024) scan1() {
    __shared__ int sh[1024];
    int t = threadIdx.x;
    int i = blockIdx.x * 1024 + t;
    int v = d_cnt[i];
    sh[t] = v;
    __syncthreads();
#pragma unroll
    for (int off = 1; off < 1024; off <<= 1) {
        int x = (t >= off) ? sh[t - off] : 0;
        __syncthreads();
        sh[t] += x;
        __syncthreads();
    }
    d_rowptr[i] = sh[t] - v;
    if (t == 1023) d_bsum[blockIdx.x] = sh[1023];
}

__global__ void __launch_bounds__(128) scan2() {
    __shared__ int sh[128];
    int t = threadIdx.x;
    int v = (t < 98) ? d_bsum[t] : 0;
    sh[t] = v;
    __syncthreads();
#pragma unroll
    for (int off = 1; off < 128; off <<= 1) {
        int x = (t >= off) ? sh[t - off] : 0;
        __syncthreads();
        sh[t] += x;
        __syncthreads();
    }
    if (t < 98) d_bscan[t] = sh[t] - v;
}

__global__ void scan3() {
    int i = blockIdx.x * 256 + threadIdx.x;
    if (i < NPAD) {
        int v = d_rowptr[i] + d_bscan[i >> 10];
        d_rowptr[i] = v;
        if (i < NN) d_woff[i] = v;
        d_cnt[i] = 0;   // reset for next run
    }
}

__global__ void scatter(const int* __restrict__ rows, const int* __restrict__ cols,
                        const float* __restrict__ vals) {
    int e = blockIdx.x * 256 + threadIdx.x;
    if (e < EE) {
        int r = rows[e];
        int pos = atomicAdd(&d_woff[r], 1);
        d_epack[pos] = make_int2(cols[e], __float_as_int(vals[e]));
    }
}

// ---------------- K1: la planes = split(logmap0(proj(expmap0(A1)))) ----------------
__global__ void __launch_bounds__(256) k1(const float* __restrict__ A1) {
    int node = blockIdx.x * 8 + (threadIdx.x >> 5);
    int lane = threadIdx.x & 31;
    float K = d_K, sq = d_sqrtK;
    const float* row = A1 + (size_t)node * 129 + 1;
    float x[4];
#pragma unroll
    for (int i = 0; i < 4; i++) x[i] = row[lane * 4 + i];
    float ss = wsum(x[0]*x[0] + x[1]*x[1] + x[2]*x[2] + x[3]*x[3]);
    float xn = fmaxf(sqrtf(ss), MIN_NORM);
    float th = xn / sq;
    float s  = sq * sinhf(th) / xn;
    float y[4];
#pragma unroll
    for (int i = 0; i < 4; i++) y[i] = s * x[i];
    float ss2 = wsum(y[0]*y[0] + y[1]*y[1] + y[2]*y[2] + y[3]*y[3]);
    float x0 = sqrtf(fmaxf(K + ss2, EPSC));
    float yn = fmaxf(sqrtf(ss2), MIN_NORM);
    float t  = fmaxf(x0 / sq, 1.0f + EPSC);
    float sc = sq * acoshf(t) / yn;
    float v[4];
#pragma unroll
    for (int i = 0; i < 4; i++) v[i] = sc * y[i];
    store_split(d_laH, d_laL, node, lane, v);
}

// ---------------- bf16 MMA GEMM, pre-split packed planes ----------------
// smem tiles: A [128 rows][16 kpairs] hi+lo (stride 20), B [16 kpairs][128 cols] hi+lo (stride 136)
#define SAW 20
#define SBW 136
#define SA_W (128 * SAW)   // 2560 words per plane buffer
#define SB_W (16 * SBW)    // 2176 words per plane buffer
#define SMEM_BYTES ((2 * (2 * SA_W + 2 * SB_W)) * 4)   // 75776

__device__ __forceinline__ void mma16(float c[4], uint32_t a0, uint32_t a1,
                                      uint32_t a2, uint32_t a3,
                                      uint32_t b0, uint32_t b1) {
    asm volatile(
        "mma.sync.aligned.m16n8k16.row.col.f32.bf16.bf16.f32 "
        "{%0,%1,%2,%3}, {%4,%5,%6,%7}, {%8,%9}, {%0,%1,%2,%3};"
        : "+f"(c[0]), "+f"(c[1]), "+f"(c[2]), "+f"(c[3])
        : "r"(a0), "r"(a1), "r"(a2), "r"(a3), "r"(b0), "r"(b1));
}

__device__ __forceinline__ void cpasync16(uint32_t saddr, const void* gptr) {
    asm volatile("cp.async.ca.shared.global [%0], [%1], 16;" :: "r"(saddr), "l"(gptr));
}

__global__ void __launch_bounds__(256, 2) mma_gemm(const uint32_t* __restrict__ AH,
                                                   const uint32_t* __restrict__ AL,
                                                   const uint32_t* __restrict__ WH,
                                                   const uint32_t* __restrict__ WL,
                                                   float* __restrict__ C, int N) {
    extern __shared__ uint32_t smem[];
    uint32_t* sAh[2] = { smem,              smem + SA_W };
    uint32_t* sAl[2] = { smem + 2 * SA_W,   smem + 3 * SA_W };
    uint32_t* sBh[2] = { smem + 4 * SA_W,            smem + 4 * SA_W + SB_W };
    uint32_t* sBl[2] = { smem + 4 * SA_W + 2 * SB_W, smem + 4 * SA_W + 3 * SB_W };

    int tid  = threadIdx.x;
    int lane = tid & 31;
    int w    = tid >> 5;
    int wm0  = (w & 3) * 32;
    int wn0  = (w >> 2) * 64;
    int r0   = blockIdx.x * 128;
    int n0   = blockIdx.y * 128;

    int a_row = tid >> 1, a_word = (tid & 1) * 8;   // 8 words of 16 per row
    int b_k   = tid >> 4, b_seg  = (tid & 15) * 8;  // 8 words of 128 per kpair row

    const uint32_t* AHp = AH + (size_t)(r0 + a_row) * 64 + a_word;
    const uint32_t* ALp = AL + (size_t)(r0 + a_row) * 64 + a_word;
    const uint32_t* WHp = WH + (size_t)b_k * N + n0 + b_seg;
    const uint32_t* WLp = WL + (size_t)b_k * N + n0 + b_seg;

    auto load_tile = [&](int buf, int kw0) {   // kw0 = kpair offset (t*16)
        uint32_t s;
        s = (uint32_t)__cvta_generic_to_shared(sAh[buf] + a_row * SAW + a_word);
        cpasync16(s,      AHp + kw0);
        cpasync16(s + 16, AHp + kw0 + 4);
        s = (uint32_t)__cvta_generic_to_shared(sAl[buf] + a_row * SAW + a_word);
        cpasync16(s,      ALp + kw0);
        cpasync16(s + 16, ALp + kw0 + 4);
        s = (uint32_t)__cvta_generic_to_shared(sBh[buf] + b_k * SBW + b_seg);
        cpasync16(s,      WHp + (size_t)kw0 * N);
        cpasync16(s + 16, WHp + (size_t)kw0 * N + 4);
        s = (uint32_t)__cvta_generic_to_shared(sBl[buf] + b_k * SBW + b_seg);
        cpasync16(s,      WLp + (size_t)kw0 * N);
        cpasync16(s + 16, WLp + (size_t)kw0 * N + 4);
        asm volatile("cp.async.commit_group;");
    };

    float acc[2][8][4];
#pragma unroll
    for (int am = 0; am < 2; am++)
#pragma unroll
        for (int n = 0; n < 8; n++)
#pragma unroll
            for (int i = 0; i < 4; i++) acc[am][n][i] = 0.0f;

    load_tile(0, 0);
    asm volatile("cp.async.wait_group 0;" ::: "memory");
    __syncthreads();

#pragma unroll
    for (int t = 0; t < 4; t++) {
        int cur = t & 1, nxt = cur ^ 1;
        if (t < 3) load_tile(nxt, (t + 1) * 16);

        const uint32_t* pAh = sAh[cur];
        const uint32_t* pAl = sAl[cur];
        const uint32_t* pBh = sBh[cur];
        const uint32_t* pBl = sBl[cur];
#pragma unroll
        for (int ks = 0; ks < 2; ks++) {
            int kq = ks * 8 + (lane & 3);
            uint32_t ah[2][4], al[2][4];
#pragma unroll
            for (int am = 0; am < 2; am++) {
                int m = wm0 + am * 16 + (lane >> 2);
                ah[am][0] = pAh[m * SAW + kq];
                ah[am][1] = pAh[(m + 8) * SAW + kq];
                ah[am][2] = pAh[m * SAW + kq + 4];
                ah[am][3] = pAh[(m + 8) * SAW + kq + 4];
                al[am][0] = pAl[m * SAW + kq];
                al[am][1] = pAl[(m + 8) * SAW + kq];
                al[am][2] = pAl[m * SAW + kq + 4];
                al[am][3] = pAl[(m + 8) * SAW + kq + 4];
            }
#pragma unroll
            for (int n = 0; n < 8; n++) {
                int c = wn0 + n * 8 + (lane >> 2);
                uint32_t bh0 = pBh[kq * SBW + c];
                uint32_t bh1 = pBh[(kq + 4) * SBW + c];
                uint32_t bl0 = pBl[kq * SBW + c];
                uint32_t bl1 = pBl[(kq + 4) * SBW + c];
#pragma unroll
                for (int am = 0; am < 2; am++) {
                    mma16(acc[am][n], al[am][0], al[am][1], al[am][2], al[am][3], bh0, bh1);
                    mma16(acc[am][n], ah[am][0], ah[am][1], ah[am][2], ah[am][3], bl0, bl1);
                    mma16(acc[am][n], ah[am][0], ah[am][1], ah[am][2], ah[am][3], bh0, bh1);
                }
            }
        }
        if (t < 3) {
            asm volatile("cp.async.wait_group 0;" ::: "memory");
        }
        __syncthreads();
    }

#pragma unroll
    for (int am = 0; am < 2; am++) {
        int mrow = r0 + wm0 + am * 16 + (lane >> 2);
#pragma unroll
        for (int n = 0; n < 8; n++) {
            int col = n0 + wn0 + n * 8 + (lane & 3) * 2;
            float2 v0 = make_float2(acc[am][n][0], acc[am][n][1]);
            float2 v1 = make_float2(acc[am][n][2], acc[am][n][3]);
            *(float2*)(C + (size_t)mrow * N + col)       = v0;
            *(float2*)(C + (size_t)(mrow + 8) * N + col) = v1;
        }
    }
}

// ---------------- K3 ----------------
__global__ void __launch_bounds__(256) k3(const float* __restrict__ nparam) {
    int node = blockIdx.x * 8 + (threadIdx.x >> 5);
    int lane = threadIdx.x & 31;
    float K = d_K, sq = d_sqrtK;
    const float* tr = d_t1p1 + (size_t)node * 256;
    float t[4], p[4];
#pragma unroll
    for (int i = 0; i < 4; i++) { t[i] = tr[lane * 4 + i]; p[i] = tr[128 + lane * 4 + i]; }

    float P[4];  float p0 = hpoint(t, P, lane, K, sq);
    float Aa[4]; float a0 = mobius_add_pt(P, p0, d_ub1, Aa, lane, K, sq);
    float l1[4]; logmap0p(Aa, a0, l1, lane, sq);
    store_h(d_la1h, node, lane, l1);

    float n = nparam[node];
    float v2[4];
#pragma unroll
    for (int i = 0; i < 4; i++) v2[i] = n * l1[i];
    float A2[4]; float a20 = hpoint(v2, A2, lane, K, sq);
    float l2[4]; logmap0p(A2, a20, l2, lane, sq);
    float* o2 = d_la2 + (size_t)node * 128 + lane * 4;
#pragma unroll
    for (int i = 0; i < 4; i++) o2[i] = l2[i];

    float Pg[4]; float pg0 = hpoint(p, Pg, lane, K, sq);
    float G[4];  float g0  = mobius_add_pt(Pg, pg0, d_ubg1, G, lane, K, sq);
    float lg[4]; logmap0p(G, g0, lg, lane, sq);
    store_h(d_gh, node, lane, lg);
}

// ---------------- fused SpMM + post chain (fp16 gathers, 4-wide MLP) ------------
__device__ __forceinline__ void edge_fma(float4& a, int2 p) {
    uint2 q = ((const uint2*)(d_gh + (size_t)p.x * 64))[threadIdx.x & 31];
    float2 ga = __half22float2(*(__half2*)&q.x);
    float2 gb = __half22float2(*(__half2*)&q.y);
    float v = __int_as_float(p.y);
    a.x = fmaf(v, ga.x, a.x);
    a.y = fmaf(v, ga.y, a.y);
    a.z = fmaf(v, gb.x, a.z);
    a.w = fmaf(v, gb.y, a.w);
}

__device__ __forceinline__ void spmm_gather(int row, int lane, float acc[4]) {
    int s = d_rowptr[row];
    int e = d_rowptr[row + 1];
    float4 a = make_float4(0.f, 0.f, 0.f, 0.f);
    int i = s;
    for (; i + 4 <= e; i += 4) {
        int2 p0 = d_epack[i];
        int2 p1 = d_epack[i + 1];
        int2 p2 = d_epack[i + 2];
        int2 p3 = d_epack[i + 3];
        uint2 q0 = ((const uint2*)(d_gh + (size_t)p0.x * 64))[lane];
        uint2 q1 = ((const uint2*)(d_gh + (size_t)p1.x * 64))[lane];
        uint2 q2 = ((const uint2*)(d_gh + (size_t)p2.x * 64))[lane];
        uint2 q3 = ((const uint2*)(d_gh + (size_t)p3.x * 64))[lane];
        float v0 = __int_as_float(p0.y), v1 = __int_as_float(p1.y);
        float v2 = __int_as_float(p2.y), v3 = __int_as_float(p3.y);
        float2 g0a = __half22float2(*(__half2*)&q0.x), g0b = __half22float2(*(__half2*)&q0.y);
        float2 g1a = __half22float2(*(__half2*)&q1.x), g1b = __half22float2(*(__half2*)&q1.y);
        float2 g2a = __half22float2(*(__half2*)&q2.x), g2b = __half22float2(*(__half2*)&q2.y);
        float2 g3a = __half22float2(*(__half2*)&q3.x), g3b = __half22float2(*(__half2*)&q3.y);
        a.x = fmaf(v0, g0a.x, fmaf(v1, g1a.x, fmaf(v2, g2a.x, fmaf(v3, g3a.x, a.x))));
        a.y = fmaf(v0, g0a.y, fmaf(v1, g1a.y, fmaf(v2, g2a.y, fmaf(v3, g3a.y, a.y))));
        a.z = fmaf(v0, g0b.x, fmaf(v1, g1b.x, fmaf(v2, g2b.x, fmaf(v3, g3b.x, a.z))));
        a.w = fmaf(v0, g0b.y, fmaf(v1, g1b.y, fmaf(v2, g2b.y, fmaf(v3, g3b.y, a.w))));
    }
    for (; i < e; i++) edge_fma(a, d_epack[i]);
    acc[0] = a.x; acc[1] = a.y; acc[2] = a.z; acc[3] = a.w;
}

__global__ void __launch_bounds__(256) spmm_l1(const float* __restrict__ nparam) {
    int row = blockIdx.x * 8 + (threadIdx.x >> 5);
    int lane = threadIdx.x & 31;
    if (row >= NN) return;
    float K = d_K, sq = d_sqrtK;
    float v[4];
    spmm_gather(row, lane, v);
    float X[4]; float x0 = hpoint(v, X, lane, K, sq);
    float l[4]; logmap0p(X, x0, l, lane, sq);
    float n = 1.0f - nparam[row];
    float v2[4];
#pragma unroll
    for (int i = 0; i < 4; i++) v2[i] = n * l[i];
    float X2[4]; float x20 = hpoint(v2, X2, lane, K, sq);
    float l2[4]; logmap0p(X2, x20, l2, lane, sq);
    const float* a2r = d_la2 + (size_t)row * 128 + lane * 4;
    float w[4];
#pragma unroll
    for (int i = 0; i < 4; i++) w[i] = l2[i] + a2r[i];
    float X3[4]; float x30 = hpoint(w, X3, lane, K, sq);
    float lx[4]; logmap0p(X3, x30, lx, lane, sq);
    store_split(d_lxH, d_lxL, row, lane, lx);
}

__global__ void __launch_bounds__(256) spmm_l2() {
    int row = blockIdx.x * 8 + (threadIdx.x >> 5);
    int lane = threadIdx.x & 31;
    if (row >= NN) return;
    float K = d_K, sq = d_sqrtK;
    float v[4];
    spmm_gather(row, lane, v);
    float X[4]; float x0 = hpoint(v, X, lane, K, sq);
    float lx[4]; logmap0p(X, x0, lx, lane, sq);
    store_h(d_lxh, row, lane, lx);
}

// ---------------- K9 ----------------
__global__ void __launch_bounds__(256) k9() {
    int node = blockIdx.x * 8 + (threadIdx.x >> 5);
    int lane = threadIdx.x & 31;
    float K = d_K, sq = d_sqrtK;
    const float* qr = d_t1p1 + (size_t)node * 128 + lane * 4;
    float q[4];
#pragma unroll
    for (int i = 0; i < 4; i++) q[i] = qr[i];
    float X[4]; float x0 = hpoint(q, X, lane, K, sq);
    float G[4]; float g0 = mobius_add_pt(X, x0, d_ubg2, G, lane, K, sq);
    float lg[4]; logmap0p(G, g0, lg, lane, sq);
    store_h(d_gh, node, lane, lg);
}

// ---------------- head ----------------
__global__ void __launch_bounds__(128) head(const int* __restrict__ bidx,
                                            const float* __restrict__ wt,
                                            const float* __restrict__ wt2,
                                            const float* __restrict__ c1w,
                                            const float* __restrict__ c1b,
                                            const float* __restrict__ c2w,
                                            const float* __restrict__ c2b,
                                            const float* __restrict__ cls,
                                            const float* __restrict__ clsb,
                                            float* __restrict__ out) {
    int b = blockIdx.x;
    int d = threadIdx.x;
    __shared__ float sg2[128], sg3[128], sel[100];
    float g2 = 0.0f, g3 = 0.0f;
    const int* bi = bidx + (size_t)b * ML;
    const __half* la1 = (const __half*)d_la1h;
    const __half* lxh = (const __half*)d_lxh;
    for (int l = 0; l < ML; l++) {
        int idx = bi[l];
        float w1 = c1w[l], w2 = c2w[l];
        g2 = fmaf(w1, __half2float(lxh[(size_t)idx * 128 + d]), g2);
        g3 = fmaf(w2, __half2float(la1[(size_t)idx * 128 + d]), g3);
    }
    sg2[d] = g2; sg3[d] = g3;
    __syncthreads();
    if (d < ML) {
        float s2 = c1b[0], s3 = c2b[0];
        for (int k = 0; k < 128; k++) {
            s2 = fmaf(sg2[k], wt [k * ML + d], s2);
            s3 = fmaf(sg3[k], wt2[k * ML + d], s3);
        }
        sel[d]      = s2;
        sel[ML + d] = s3;
        out[BB + (size_t)b * 100 + d]      = s2;
        out[BB + (size_t)b * 100 + ML + d] = s3;
    }
    __syncthreads();
    if (d == 0) {
        float best = -3.4e38f;
        int bj = 0;
        for (int j = 0; j < 5; j++) {
            float p = clsb[j];
            for (int i = 0; i < 100; i++) p = fmaf(sel[i], cls[i * 5 + j], p);
            if (p > best) { best = p; bj = j; }
        }
        out[b] = (float)bj;
    }
}

// ---------------- launch ----------------
extern "C" void kernel_launch(void* const* d_in, const int* in_sizes, int n_in,
                              void* d_out, int out_size) {
    const float* A1   = (const float*)d_in[0];
    const int*   rows = (const int*)  d_in[1];
    const int*   cols = (const int*)  d_in[2];
    const float* vals = (const float*)d_in[3];
    const int*   bidx = (const int*)  d_in[4];
    const float* rc   = (const float*)d_in[5];
    const float* np   = (const float*)d_in[6];
    const float* Lin1 = (const float*)d_in[7];
    const float* L1b  = (const float*)d_in[8];
    const float* g1w  = (const float*)d_in[9];
    const float* g1b  = (const float*)d_in[10];
    const float* g2w  = (const float*)d_in[11];
    const float* g2b  = (const float*)d_in[12];
    const float* wt   = (const float*)d_in[13];
    const float* wt2  = (const float*)d_in[14];
    const float* c1w  = (const float*)d_in[15];
    const float* c1b  = (const float*)d_in[16];
    const float* c2w  = (const float*)d_in[17];
    const float* c2b  = (const float*)d_in[18];
    const float* cls  = (const float*)d_in[19];
    const float* clsb = (const float*)d_in[20];
    float* out = (float*)d_out;

    float*    p_t1p1;  cudaGetSymbolAddress((void**)&p_t1p1,  d_t1p1);
    uint32_t* p_laH;   cudaGetSymbolAddress((void**)&p_laH,   d_laH);
    uint32_t* p_laL;   cudaGetSymbolAddress((void**)&p_laL,   d_laL);
    uint32_t* p_lxH;   cudaGetSymbolAddress((void**)&p_lxH,   d_lxH);
    uint32_t* p_lxL;   cudaGetSymbolAddress((void**)&p_lxL,   d_lxL);
    uint32_t* p_wcH;   cudaGetSymbolAddress((void**)&p_wcH,   d_WcatH);
    uint32_t* p_wcL;   cudaGetSymbolAddress((void**)&p_wcL,   d_WcatL);
    uint32_t* p_w2H;   cudaGetSymbolAddress((void**)&p_w2H,   d_W2H);
    uint32_t* p_w2L;   cudaGetSymbolAddress((void**)&p_w2L,   d_W2L);

    cudaFuncSetAttribute(mma_gemm, cudaFuncAttributeMaxDynamicSharedMemorySize, SMEM_BYTES);

    k0<<<1, 1>>>(rc, L1b, g1b, g2b);
    prep_wcat<<<64, 256>>>(Lin1, g1w);
    k1<<<12500, 256>>>(A1);
    mma_gemm<<<dim3(782, 2), 256, SMEM_BYTES>>>(p_laH, p_laL, p_wcH, p_wcL, p_t1p1, 256);  // #4 profiled
    k3<<<12500, 256>>>(np);
    prep_w2<<<32, 256>>>(g2w);

    // CSR build (reused by both aggregation passes)
    hist<<<(EE + 255) / 256, 256>>>(rows);
    scan1<<<98, 1024>>>();
    scan2<<<1, 128>>>();
    scan3<<<(NPAD + 255) / 256, 256>>>();
    scatter<<<(EE + 255) / 256, 256>>>(rows, cols, vals);

    spmm_l1<<<12500, 256>>>(np);
    mma_gemm<<<dim3(782, 1), 256, SMEM_BYTES>>>(p_lxH, p_lxL, p_w2H, p_w2L, p_t1p1, 128);
    k9<<<12500, 256>>>();
    spmm_l2<<<12500, 256>>>();
    head<<<BB, 128>>>(bidx, wt, wt2, c1w, c1b, c2w, c2b, cls, clsb, out);
}